// round 3
// baseline (speedup 1.0000x reference)
#include <cuda_runtime.h>
#include <math.h>
#include <stdint.h>

// ---------------- problem constants ----------------
#define cN 10000
#define cE 40000
#define cD 64
#define cB 512
#define cFIN 11
#define cEF 5
#define cH 128
#define cDSQ 4096

// ---------------- device scratch ----------------
__device__ float g_h0[cN * cD];
__device__ float g_h1[cN * cD];
__device__ float g_hrelu[cE * cH];            // 20 MB
__device__ uint32_t g_Bmat[cH * cD * cD];     // [8192][64] tf32 bits, 2 MB
__device__ float g_bmsg[cN * cD];
__device__ float g_agg[cN * cD];
__device__ float g_m[cN * cD];
__device__ float g_CG[cN * 4 * cD];           // [N,256] = [croot | G2]
__device__ float g_G1[cN * 3 * cD];
__device__ float g_Wcat[cD * 4 * cD];         // [64,256]
__device__ float g_bcat[4 * cD];
__device__ float g_deg[cN];
__device__ float g_esc[cN];
__device__ unsigned g_emaxu[cB];
__device__ float g_esum[cB];
__device__ float g_rvec[cB * cD];
__device__ float g_qsA[cB * 2 * cD];
__device__ float g_qsB[cB * 2 * cD];
__device__ float g_hlA[cB * cD];
__device__ float g_hlB[cB * cD];
__device__ float g_clA[cB * cD];
__device__ float g_clB[cB * cD];

// ---------------- helpers ----------------
__device__ __forceinline__ float sigm(float x) { return 1.0f / (1.0f + expf(-x)); }

__device__ __forceinline__ unsigned f2u(float f) {
    unsigned u = __float_as_uint(f);
    return (u & 0x80000000u) ? ~u : (u | 0x80000000u);
}
__device__ __forceinline__ float u2f(unsigned u) {
    return __uint_as_float((u & 0x80000000u) ? (u ^ 0x80000000u) : ~u);
}
__device__ __forceinline__ uint32_t f2tf32(float f) {
    uint32_t u;
    asm("cvt.rna.tf32.f32 %0, %1;" : "=r"(u) : "f"(f));
    return u;
}
__device__ __forceinline__ void mma_tf32(float* d, const uint32_t* a, const uint32_t* b) {
    asm volatile(
        "mma.sync.aligned.m16n8k8.row.col.f32.tf32.tf32.f32 "
        "{%0,%1,%2,%3}, {%4,%5,%6,%7}, {%8,%9}, {%0,%1,%2,%3};"
        : "+f"(d[0]), "+f"(d[1]), "+f"(d[2]), "+f"(d[3])
        : "r"(a[0]), "r"(a[1]), "r"(a[2]), "r"(a[3]), "r"(b[0]), "r"(b[1]));
}
__device__ __forceinline__ void cp16(void* smem, const void* gmem) {
    uint32_t s = (uint32_t)__cvta_generic_to_shared(smem);
    asm volatile("cp.async.ca.shared.global [%0], [%1], 16;" :: "r"(s), "l"(gmem));
}

// ---------------- small kernels ----------------
__global__ void k_zero(float* p, int n) {
    int i = blockIdx.x * blockDim.x + threadIdx.x;
    if (i < n) p[i] = 0.0f;
}
__global__ void k_deg_zero(float* deg) {
    int i = blockIdx.x * blockDim.x + threadIdx.x;
    if (i < cN) deg[i] = 0.0f;
}
__global__ void k_deg(const int* __restrict__ dst, float* deg) {
    int e = blockIdx.x * blockDim.x + threadIdx.x;
    if (e < cE) atomicAdd(&deg[dst[e]], 1.0f);
}
__global__ void k_lin0(const float* __restrict__ x, const float* __restrict__ w,
                       const float* __restrict__ b, float* __restrict__ h0) {
    int idx = blockIdx.x * blockDim.x + threadIdx.x;
    if (idx >= cN * cD) return;
    int n = idx >> 6, d = idx & 63;
    float acc = b[d];
    const float* xr = x + n * cFIN;
#pragma unroll
    for (int i = 0; i < cFIN; i++) acc += xr[i] * w[i * cD + d];
    h0[idx] = fmaxf(acc, 0.0f);
}
__global__ void k_edge1(const float* __restrict__ ea, const float* __restrict__ w1,
                        const float* __restrict__ b1, float* __restrict__ hrelu) {
    int idx = blockIdx.x * blockDim.x + threadIdx.x;
    if (idx >= cE * cH) return;
    int e = idx >> 7, j = idx & 127;
    float acc = b1[j];
    const float* er = ea + e * cEF;
#pragma unroll
    for (int i = 0; i < cEF; i++) acc += er[i] * w1[i * cH + j];
    hrelu[idx] = fmaxf(acc, 0.0f);
}

// Bmat[(i*128+k)*64 + o] = tf32(net_w2[k*4096 + i*64 + o])
__global__ void k_prepB(const float* __restrict__ w2, uint32_t* __restrict__ Bmat) {
    int idx = blockIdx.x * blockDim.x + threadIdx.x;
    if (idx >= cH * cDSQ) return;
    int kap = idx >> 6, o = idx & 63;
    int i = kap >> 7, k = kap & 127;
    Bmat[idx] = f2tf32(w2[(size_t)k * cDSQ + i * cD + o]);
}
// Wcat [64][256] = [conv_root | gru_w_hh]; bcat [256] = [0 | gru_b_hh]
__global__ void k_prepW(const float* __restrict__ wroot, const float* __restrict__ whh,
                        const float* __restrict__ bhh,
                        float* __restrict__ Wcat, float* __restrict__ bcat) {
    int idx = blockIdx.x * blockDim.x + threadIdx.x;
    if (idx < cD * 4 * cD) {
        int k = idx >> 8, col = idx & 255;
        Wcat[idx] = (col < cD) ? wroot[k * cD + col] : whh[k * 3 * cD + (col - cD)];
    }
    if (idx < 4 * cD) bcat[idx] = (idx < cD) ? 0.0f : bhh[idx - cD];
}

// -------- generic tiled SGEMM (small node GEMMs) --------
template <int BM, int BN, int BK, int TM, int TN>
__global__ void sgemm(int M, int Nc, int K,
                      const float* __restrict__ A, const float* __restrict__ Bw,
                      const float* __restrict__ bias, float* __restrict__ C) {
    constexpr int NT = (BM / TM) * (BN / TN);
    __shared__ float As[BK][BM];
    __shared__ float Bs[BK][BN];
    const int tid = threadIdx.x;
    const int tcn = BN / TN;
    const int tr = tid / tcn, tc = tid % tcn;
    const int rowBase = blockIdx.y * BM, colBase = blockIdx.x * BN;

    float acc[TM][TN];
#pragma unroll
    for (int i = 0; i < TM; i++)
#pragma unroll
        for (int j = 0; j < TN; j++) acc[i][j] = 0.0f;

    for (int k0 = 0; k0 < K; k0 += BK) {
#pragma unroll
        for (int i = tid; i < BM * BK; i += NT) {
            int r = i / BK, kk = i % BK;
            int gr = rowBase + r;
            As[kk][r] = (gr < M) ? A[(size_t)gr * K + k0 + kk] : 0.0f;
        }
#pragma unroll
        for (int i = tid; i < BK * BN; i += NT) {
            int kk = i / BN, cc2 = i % BN;
            int gc = colBase + cc2;
            Bs[kk][cc2] = (gc < Nc) ? Bw[(size_t)(k0 + kk) * Nc + gc] : 0.0f;
        }
        __syncthreads();
#pragma unroll
        for (int kk = 0; kk < BK; kk++) {
            float ra[TM], rb[TN];
#pragma unroll
            for (int i = 0; i < TM; i++) ra[i] = As[kk][tr * TM + i];
#pragma unroll
            for (int j = 0; j < TN; j++) rb[j] = Bs[kk][tc * TN + j];
#pragma unroll
            for (int i = 0; i < TM; i++)
#pragma unroll
                for (int j = 0; j < TN; j++) acc[i][j] += ra[i] * rb[j];
        }
        __syncthreads();
    }
#pragma unroll
    for (int i = 0; i < TM; i++) {
        int r = rowBase + tr * TM + i;
        if (r >= M) continue;
#pragma unroll
        for (int j = 0; j < TN; j++) {
            int cc2 = colBase + tc * TN + j;
            if (cc2 >= Nc) continue;
            float v = acc[i][j] + (bias ? bias[cc2] : 0.0f);
            C[(size_t)r * Nc + cc2] = v;
        }
    }
}

// -------- fused outer-product GEMM: agg[dst] += (out[src] (x) hrelu[e]) @ Bmat + bmsg[src] --------
// 128 edges per CTA, 4 warps, warp tile 32m x 64n, K = 64 i-blocks x 128 k.
#define MSO 68    // out_s row pitch (floats)
#define MSH 132   // hrelu_s row pitch
#define MSB 68    // Bs row pitch (u32)
__global__ void __launch_bounds__(128) k_msgemm(
    const float* __restrict__ outF, const float* __restrict__ hrelu,
    const uint32_t* __restrict__ Bmat, const float* __restrict__ bmsg,
    const int* __restrict__ src, const int* __restrict__ dst,
    float* __restrict__ agg)
{
    extern __shared__ char sm_raw[];
    float* out_s   = (float*)sm_raw;                            // [128][68]  34816 B
    float* hrelu_s = (float*)(sm_raw + 34816);                  // [128][132] 67584 B
    uint32_t* BsBuf = (uint32_t*)(sm_raw + 34816 + 67584);      // [2][128][68] 69632 B
    int* src_s = (int*)(sm_raw + 34816 + 67584 + 69632);        // [128]
    int* dst_s = src_s + 128;

    const int tid = threadIdx.x;
    const int warp = tid >> 5, lane = tid & 31;
    const int g = lane >> 2, c = lane & 3;
    const int e0 = blockIdx.x * 128;

    // gather per-edge data: thread t -> edge row t
    {
        int e = e0 + tid;
        bool valid = (e < cE);
        int s = valid ? src[e] : 0;
        int d = valid ? dst[e] : 0;
        src_s[tid] = s; dst_s[tid] = d;
        const float4* orow = (const float4*)(outF + (size_t)s * cD);
        const float4* hrow = (const float4*)(hrelu + (size_t)e * cH);
        float4 z4 = make_float4(0.f, 0.f, 0.f, 0.f);
#pragma unroll
        for (int q = 0; q < 16; q++)
            *(float4*)&out_s[tid * MSO + q * 4] = valid ? orow[q] : z4;
#pragma unroll
        for (int q = 0; q < 32; q++)
            *(float4*)&hrelu_s[tid * MSH + q * 4] = valid ? hrow[q] : z4;
    }

    // prefetch B i-block 0
    {
        const uint32_t* gsrc = Bmat + (size_t)tid * cD;   // i=0, row tid
        uint32_t* dstp = BsBuf + tid * MSB;
#pragma unroll
        for (int q = 0; q < 16; q++) cp16(dstp + q * 4, gsrc + q * 4);
        asm volatile("cp.async.commit_group;");
    }

    float acc[2][8][4];
#pragma unroll
    for (int mt = 0; mt < 2; mt++)
#pragma unroll
        for (int nt = 0; nt < 8; nt++)
#pragma unroll
            for (int j = 0; j < 4; j++) acc[mt][nt][j] = 0.0f;

    const int r0 = warp * 32;

    for (int i = 0; i < cD; i++) {
        // prefetch next i-block into other buffer
        if (i < cD - 1) {
            const uint32_t* gsrc = Bmat + ((size_t)(i + 1) * cH + tid) * cD;
            uint32_t* dstp = BsBuf + ((i + 1) & 1) * (128 * MSB) + tid * MSB;
#pragma unroll
            for (int q = 0; q < 16; q++) cp16(dstp + q * 4, gsrc + q * 4);
            asm volatile("cp.async.commit_group;");
            asm volatile("cp.async.wait_group 1;");
        } else {
            asm volatile("cp.async.wait_group 0;");
        }
        __syncthreads();

        const uint32_t* Bb = BsBuf + (i & 1) * (128 * MSB);
        // hoist out values for this i
        float o00 = out_s[(r0 + g) * MSO + i];
        float o01 = out_s[(r0 + 8 + g) * MSO + i];
        float o10 = out_s[(r0 + 16 + g) * MSO + i];
        float o11 = out_s[(r0 + 24 + g) * MSO + i];
        const float* h00 = &hrelu_s[(r0 + g) * MSH];
        const float* h01 = &hrelu_s[(r0 + 8 + g) * MSH];
        const float* h10 = &hrelu_s[(r0 + 16 + g) * MSH];
        const float* h11 = &hrelu_s[(r0 + 24 + g) * MSH];

#pragma unroll
        for (int k0 = 0; k0 < cH; k0 += 8) {
            uint32_t af[2][4];
            af[0][0] = f2tf32(o00 * h00[k0 + c]);
            af[0][1] = f2tf32(o01 * h01[k0 + c]);
            af[0][2] = f2tf32(o00 * h00[k0 + c + 4]);
            af[0][3] = f2tf32(o01 * h01[k0 + c + 4]);
            af[1][0] = f2tf32(o10 * h10[k0 + c]);
            af[1][1] = f2tf32(o11 * h11[k0 + c]);
            af[1][2] = f2tf32(o10 * h10[k0 + c + 4]);
            af[1][3] = f2tf32(o11 * h11[k0 + c + 4]);
#pragma unroll
            for (int nt = 0; nt < 8; nt++) {
                uint32_t bf[2];
                bf[0] = Bb[(k0 + c) * MSB + nt * 8 + g];
                bf[1] = Bb[(k0 + c + 4) * MSB + nt * 8 + g];
                mma_tf32(acc[0][nt], af[0], bf);
                mma_tf32(acc[1][nt], af[1], bf);
            }
        }
        __syncthreads();
    }

    // epilogue: add per-edge bias (bmsg[src]) and scatter-atomic into agg[dst]
#pragma unroll
    for (int mt = 0; mt < 2; mt++) {
        int rl0 = r0 + mt * 16 + g;
        int rl1 = rl0 + 8;
        bool v0 = (e0 + rl0 < cE), v1 = (e0 + rl1 < cE);
        int dn0 = dst_s[rl0], sn0 = src_s[rl0];
        int dn1 = dst_s[rl1], sn1 = src_s[rl1];
        const float* bm0 = bmsg + (size_t)sn0 * cD;
        const float* bm1 = bmsg + (size_t)sn1 * cD;
        float* a0 = agg + (size_t)dn0 * cD;
        float* a1 = agg + (size_t)dn1 * cD;
#pragma unroll
        for (int nt = 0; nt < 8; nt++) {
            int col = nt * 8 + c * 2;
            if (v0) {
                atomicAdd(&a0[col],     acc[mt][nt][0] + bm0[col]);
                atomicAdd(&a0[col + 1], acc[mt][nt][1] + bm0[col + 1]);
            }
            if (v1) {
                atomicAdd(&a1[col],     acc[mt][nt][2] + bm1[col]);
                atomicAdd(&a1[col + 1], acc[mt][nt][3] + bm1[col + 1]);
            }
        }
    }
}

// m = relu(agg/deg + CG[:,0:64] + conv_bias)
__global__ void k_m(const float* __restrict__ agg, const float* __restrict__ CG,
                    const float* __restrict__ deg, const float* __restrict__ cbias,
                    float* __restrict__ m) {
    int idx = blockIdx.x * blockDim.x + threadIdx.x;
    if (idx >= cN * cD) return;
    int n = idx >> 6, d = idx & 63;
    float dg = fmaxf(deg[n], 1.0f);
    float v = agg[idx] / dg + CG[(size_t)n * 4 * cD + d] + cbias[d];
    m[idx] = fmaxf(v, 0.0f);
}

// GRU gates: G1 [N,192]; G2 = CG[:,64:256]
__global__ void k_gate(const float* __restrict__ G1, const float* __restrict__ CG,
                       const float* __restrict__ h, float* __restrict__ hn) {
    int idx = blockIdx.x * blockDim.x + threadIdx.x;
    if (idx >= cN * cD) return;
    int n = idx >> 6, d = idx & 63;
    const float* g1 = G1 + (size_t)n * 3 * cD;
    const float* g2 = CG + (size_t)n * 4 * cD + cD;
    float r = sigm(g1[d] + g2[d]);
    float z = sigm(g1[cD + d] + g2[cD + d]);
    float nn = tanhf(g1[2 * cD + d] + r * g2[2 * cD + d]);
    hn[idx] = (1.0f - z) * nn + z * h[idx];
}

// ---------------- Set2Set ----------------
__global__ void k_s2s_init(float* qsA, float* hlA, float* clA) {
    int i = blockIdx.x * blockDim.x + threadIdx.x;
    if (i < cB * 2 * cD) qsA[i] = 0.0f;
    if (i < cB * cD) { hlA[i] = 0.0f; clA[i] = 0.0f; }
}
__global__ void k_lstm(const float* __restrict__ qs, const float* __restrict__ hl,
                       const float* __restrict__ cl,
                       const float* __restrict__ w_ih, const float* __restrict__ w_hh,
                       const float* __restrict__ b_ih, const float* __restrict__ b_hh,
                       float* __restrict__ hl_n, float* __restrict__ cl_n) {
    int idx = blockIdx.x * blockDim.x + threadIdx.x;
    if (idx >= cB * cD) return;
    int b = idx >> 6, d = idx & 63;
    float acc0 = b_ih[d] + b_hh[d];
    float acc1 = b_ih[cD + d] + b_hh[cD + d];
    float acc2 = b_ih[2 * cD + d] + b_hh[2 * cD + d];
    float acc3 = b_ih[3 * cD + d] + b_hh[3 * cD + d];
    const float* q = qs + b * 2 * cD;
#pragma unroll 4
    for (int k = 0; k < 2 * cD; k++) {
        float qv = q[k];
        const float* wr = w_ih + k * 4 * cD;
        acc0 += qv * wr[d]; acc1 += qv * wr[cD + d];
        acc2 += qv * wr[2 * cD + d]; acc3 += qv * wr[3 * cD + d];
    }
    const float* hr = hl + b * cD;
#pragma unroll 4
    for (int k = 0; k < cD; k++) {
        float hv = hr[k];
        const float* wr = w_hh + k * 4 * cD;
        acc0 += hv * wr[d]; acc1 += hv * wr[cD + d];
        acc2 += hv * wr[2 * cD + d]; acc3 += hv * wr[3 * cD + d];
    }
    float ig = sigm(acc0), fg = sigm(acc1), gg = tanhf(acc2), og = sigm(acc3);
    float cc2 = fg * cl[idx] + ig * gg;
    cl_n[idx] = cc2;
    hl_n[idx] = og * tanhf(cc2);
}
__global__ void k_zero_bat(unsigned* emaxu, float* esum, float* rvec) {
    int i = blockIdx.x * blockDim.x + threadIdx.x;
    if (i < cB) { emaxu[i] = 0u; esum[i] = 0.0f; }
    if (i < cB * cD) rvec[i] = 0.0f;
}
__global__ void k_attn1(const float* __restrict__ out, const int* __restrict__ batch,
                        const float* __restrict__ hl, float* __restrict__ esc,
                        unsigned* __restrict__ emaxu) {
    int n = blockIdx.x * blockDim.x + threadIdx.x;
    if (n >= cN) return;
    int b = batch[n];
    const float* o = out + n * cD;
    const float* q = hl + b * cD;
    float acc = 0.0f;
#pragma unroll 8
    for (int d = 0; d < cD; d++) acc += o[d] * q[d];
    esc[n] = acc;
    atomicMax(&emaxu[b], f2u(acc));
}
__global__ void k_attn2(const int* __restrict__ batch, float* __restrict__ esc,
                        const unsigned* __restrict__ emaxu, float* __restrict__ esum) {
    int n = blockIdx.x * blockDim.x + threadIdx.x;
    if (n >= cN) return;
    int b = batch[n];
    float ee = expf(esc[n] - u2f(emaxu[b]));
    esc[n] = ee;
    atomicAdd(&esum[b], ee);
}
__global__ void k_attn3(const float* __restrict__ out, const int* __restrict__ batch,
                        const float* __restrict__ esc, const float* __restrict__ esum,
                        float* __restrict__ rvec) {
    int idx = blockIdx.x * blockDim.x + threadIdx.x;
    if (idx >= cN * cD) return;
    int n = idx >> 6, d = idx & 63;
    int b = batch[n];
    float a = esc[n] / esum[b];
    atomicAdd(&rvec[b * cD + d], a * out[idx]);
}
__global__ void k_qstar(const float* __restrict__ hl, const float* __restrict__ rvec,
                        float* __restrict__ qs_n) {
    int idx = blockIdx.x * blockDim.x + threadIdx.x;
    if (idx >= cB * 2 * cD) return;
    int b = idx >> 7, c = idx & 127;
    qs_n[idx] = (c < cD) ? hl[b * cD + c] : rvec[b * cD + (c - cD)];
}
__global__ void k_lin1(const float* __restrict__ qs, const float* __restrict__ w,
                       const float* __restrict__ b, float* __restrict__ out) {
    int idx = blockIdx.x * blockDim.x + threadIdx.x;
    if (idx >= cB * cD) return;
    int bb = idx >> 6, d = idx & 63;
    float acc = b[d];
    const float* q = qs + bb * 2 * cD;
#pragma unroll 8
    for (int k = 0; k < 2 * cD; k++) acc += q[k] * w[k * cD + d];
    out[idx] = fmaxf(acc, 0.0f);
}

// ---------------- launch ----------------
extern "C" void kernel_launch(void* const* d_in, const int* in_sizes, int n_in,
                              void* d_out, int out_size) {
    const float* x        = (const float*)d_in[0];
    const float* ea       = (const float*)d_in[1];
    const int*   ei       = (const int*)d_in[2];
    const int*   batch    = (const int*)d_in[3];
    const float* lin0_w   = (const float*)d_in[4];
    const float* lin0_b   = (const float*)d_in[5];
    const float* net_w1   = (const float*)d_in[6];
    const float* net_b1   = (const float*)d_in[7];
    const float* net_w2   = (const float*)d_in[8];
    const float* net_b2   = (const float*)d_in[9];
    const float* conv_root= (const float*)d_in[10];
    const float* conv_bias= (const float*)d_in[11];
    const float* gru_w_ih = (const float*)d_in[12];
    const float* gru_w_hh = (const float*)d_in[13];
    const float* gru_b_ih = (const float*)d_in[14];
    const float* gru_b_hh = (const float*)d_in[15];
    const float* lstm_w_ih= (const float*)d_in[16];
    const float* lstm_w_hh= (const float*)d_in[17];
    const float* lstm_b_ih= (const float*)d_in[18];
    const float* lstm_b_hh= (const float*)d_in[19];
    const float* lin1_w   = (const float*)d_in[20];
    const float* lin1_b   = (const float*)d_in[21];
    float* out = (float*)d_out;

    const int* src = ei;
    const int* dst = ei + cE;

    void* p;
    cudaGetSymbolAddress(&p, g_h0);    float* p_h0 = (float*)p;
    cudaGetSymbolAddress(&p, g_h1);    float* p_h1 = (float*)p;
    cudaGetSymbolAddress(&p, g_hrelu); float* p_hr = (float*)p;
    cudaGetSymbolAddress(&p, g_Bmat);  uint32_t* p_Bmat = (uint32_t*)p;
    cudaGetSymbolAddress(&p, g_bmsg);  float* p_bmsg = (float*)p;
    cudaGetSymbolAddress(&p, g_agg);   float* p_agg = (float*)p;
    cudaGetSymbolAddress(&p, g_m);     float* p_m = (float*)p;
    cudaGetSymbolAddress(&p, g_CG);    float* p_CG = (float*)p;
    cudaGetSymbolAddress(&p, g_G1);    float* p_G1 = (float*)p;
    cudaGetSymbolAddress(&p, g_Wcat);  float* p_Wcat = (float*)p;
    cudaGetSymbolAddress(&p, g_bcat);  float* p_bcat = (float*)p;
    cudaGetSymbolAddress(&p, g_deg);   float* p_deg = (float*)p;
    cudaGetSymbolAddress(&p, g_esc);   float* p_esc = (float*)p;
    cudaGetSymbolAddress(&p, g_emaxu); unsigned* p_emax = (unsigned*)p;
    cudaGetSymbolAddress(&p, g_esum);  float* p_esum = (float*)p;
    cudaGetSymbolAddress(&p, g_rvec);  float* p_rvec = (float*)p;
    cudaGetSymbolAddress(&p, g_qsA);   float* p_qsA = (float*)p;
    cudaGetSymbolAddress(&p, g_qsB);   float* p_qsB = (float*)p;
    cudaGetSymbolAddress(&p, g_hlA);   float* p_hlA = (float*)p;
    cudaGetSymbolAddress(&p, g_hlB);   float* p_hlB = (float*)p;
    cudaGetSymbolAddress(&p, g_clA);   float* p_clA = (float*)p;
    cudaGetSymbolAddress(&p, g_clB);   float* p_clB = (float*)p;

    const int T = 256;
    const int MS_SMEM = 34816 + 67584 + 69632 + 1024;   // 173056 B
    cudaFuncSetAttribute(k_msgemm, cudaFuncAttributeMaxDynamicSharedMemorySize, MS_SMEM);

    // degree
    k_deg_zero<<<(cN + T - 1) / T, T>>>(p_deg);
    k_deg<<<(cE + T - 1) / T, T>>>(dst, p_deg);

    // lin0 -> h0
    k_lin0<<<(cN * cD + T - 1) / T, T>>>(x, lin0_w, lin0_b, p_h0);

    // edge net layer 1 + preps
    k_edge1<<<(cE * cH + T - 1) / T, T>>>(ea, net_w1, net_b1, p_hr);
    k_prepB<<<(cH * cDSQ + T - 1) / T, T>>>(net_w2, p_Bmat);
    k_prepW<<<(cD * 4 * cD + T - 1) / T, T>>>(conv_root, gru_w_hh, gru_b_hh, p_Wcat, p_bcat);

    // 3 message-passing steps
    for (int s = 0; s < 3; s++) {
        float* cur = (s & 1) ? p_h1 : p_h0;
        float* nxt = (s & 1) ? p_h0 : p_h1;

        k_zero<<<(cN * cD + T - 1) / T, T>>>(p_agg, cN * cD);
        // bias_msg = cur @ B2  (net_b2 viewed as [64,64])
        {
            dim3 grid(1, (cN + 63) / 64);
            sgemm<64, 64, 8, 4, 4><<<grid, 256>>>(cN, cD, cD, cur, net_b2, (const float*)0, p_bmsg);
        }
        // fused outer-product GEMM + scatter
        k_msgemm<<<(cE + 127) / 128, 128, MS_SMEM>>>(cur, p_hr, p_Bmat, p_bmsg, src, dst, p_agg);
        // CG = cur @ Wcat + bcat  -> [croot | G2]
        {
            dim3 grid(4, (cN + 63) / 64);
            sgemm<64, 64, 8, 4, 4><<<grid, 256>>>(cN, 4 * cD, cD, cur, p_Wcat, p_bcat, p_CG);
        }
        k_m<<<(cN * cD + T - 1) / T, T>>>(p_agg, p_CG, p_deg, conv_bias, p_m);
        // G1 = m @ gru_w_ih + b_ih
        {
            dim3 grid(3, (cN + 63) / 64);
            sgemm<64, 64, 8, 4, 4><<<grid, 256>>>(cN, 3 * cD, cD, p_m, gru_w_ih, gru_b_ih, p_G1);
        }
        k_gate<<<(cN * cD + T - 1) / T, T>>>(p_G1, p_CG, cur, nxt);
    }
    float* p_hfin = p_h1;

    // Set2Set
    k_s2s_init<<<(cB * 2 * cD + T - 1) / T, T>>>(p_qsA, p_hlA, p_clA);
    for (int t = 0; t < 3; t++) {
        float* qs_c = (t & 1) ? p_qsB : p_qsA;
        float* qs_n = (t & 1) ? p_qsA : p_qsB;
        float* hl_c = (t & 1) ? p_hlB : p_hlA;
        float* hl_n = (t & 1) ? p_hlA : p_hlB;
        float* cl_c = (t & 1) ? p_clB : p_clA;
        float* cl_n = (t & 1) ? p_clA : p_clB;

        k_lstm<<<(cB * cD + T - 1) / T, T>>>(qs_c, hl_c, cl_c, lstm_w_ih, lstm_w_hh,
                                             lstm_b_ih, lstm_b_hh, hl_n, cl_n);
        k_zero_bat<<<(cB * cD + T - 1) / T, T>>>(p_emax, p_esum, p_rvec);
        k_attn1<<<(cN + T - 1) / T, T>>>(p_hfin, batch, hl_n, p_esc, p_emax);
        k_attn2<<<(cN + T - 1) / T, T>>>(batch, p_esc, p_emax, p_esum);
        k_attn3<<<(cN * cD + T - 1) / T, T>>>(p_hfin, batch, p_esc, p_esum, p_rvec);
        k_qstar<<<(cB * 2 * cD + T - 1) / T, T>>>(hl_n, p_rvec, qs_n);
    }

    k_lin1<<<(cB * cD + T - 1) / T, T>>>(p_qsB, lin1_w, lin1_b, out);
}

// round 6
// speedup vs baseline: 2.1528x; 2.1528x over previous
#include <cuda_runtime.h>
#include <cuda_fp16.h>
#include <math.h>
#include <stdint.h>

// ---------------- problem constants ----------------
#define cN 10000
#define cE 40000
#define cD 64
#define cB 512
#define cFIN 11
#define cEF 5
#define cH 128
#define cDSQ 4096

// ---------------- device scratch ----------------
__device__ float g_h0[cN * cD];
__device__ float g_h1[cN * cD];
__device__ float g_hrelu[cE * cH];            // 20 MB
__device__ __half g_ewh[(size_t)cE * cDSQ];   // 320 MB fp16 edge weights (bias folded in)
__device__ float g_agg[cN * cD];
__device__ float g_m[cN * cD];
__device__ float g_CG[cN * 4 * cD];           // [N,256] = [croot | G2]
__device__ float g_G1[cN * 3 * cD];
__device__ float g_Wcat[cD * 4 * cD];         // [64,256] = [conv_root | gru_w_hh]
__device__ float g_bcat[4 * cD];
__device__ float g_deg[cN];
__device__ float g_esc[cN];
__device__ unsigned g_emaxu[cB];
__device__ float g_esum[cB];
__device__ float g_rvec[cB * cD];
__device__ float g_qsA[cB * 2 * cD];
__device__ float g_qsB[cB * 2 * cD];
__device__ float g_hlA[cB * cD];
__device__ float g_hlB[cB * cD];
__device__ float g_clA[cB * cD];
__device__ float g_clB[cB * cD];

// ---------------- helpers ----------------
__device__ __forceinline__ float sigm(float x) { return 1.0f / (1.0f + expf(-x)); }

__device__ __forceinline__ unsigned f2u(float f) {
    unsigned u = __float_as_uint(f);
    return (u & 0x80000000u) ? ~u : (u | 0x80000000u);
}
__device__ __forceinline__ float u2f(unsigned u) {
    return __uint_as_float((u & 0x80000000u) ? (u ^ 0x80000000u) : ~u);
}
__device__ __forceinline__ uint32_t f2tf32(float f) {
    uint32_t u;
    asm("cvt.rna.tf32.f32 %0, %1;" : "=r"(u) : "f"(f));
    return u;
}
__device__ __forceinline__ void mma_tf32(float* d, const uint32_t* a, const uint32_t* b) {
    asm volatile(
        "mma.sync.aligned.m16n8k8.row.col.f32.tf32.tf32.f32 "
        "{%0,%1,%2,%3}, {%4,%5,%6,%7}, {%8,%9}, {%0,%1,%2,%3};"
        : "+f"(d[0]), "+f"(d[1]), "+f"(d[2]), "+f"(d[3])
        : "r"(a[0]), "r"(a[1]), "r"(a[2]), "r"(a[3]), "r"(b[0]), "r"(b[1]));
}

// ---------------- small kernels ----------------
__global__ void k_zero(float* p, int n) {
    int i = blockIdx.x * blockDim.x + threadIdx.x;
    if (i < n) p[i] = 0.0f;
}
__global__ void k_deg_zero(float* deg) {
    int i = blockIdx.x * blockDim.x + threadIdx.x;
    if (i < cN) deg[i] = 0.0f;
}
__global__ void k_deg(const int* __restrict__ dst, float* deg) {
    int e = blockIdx.x * blockDim.x + threadIdx.x;
    if (e < cE) atomicAdd(&deg[dst[e]], 1.0f);
}
__global__ void k_lin0(const float* __restrict__ x, const float* __restrict__ w,
                       const float* __restrict__ b, float* __restrict__ h0) {
    int idx = blockIdx.x * blockDim.x + threadIdx.x;
    if (idx >= cN * cD) return;
    int n = idx >> 6, d = idx & 63;
    float acc = b[d];
    const float* xr = x + n * cFIN;
#pragma unroll
    for (int i = 0; i < cFIN; i++) acc += xr[i] * w[i * cD + d];
    h0[idx] = fmaxf(acc, 0.0f);
}
__global__ void k_edge1(const float* __restrict__ ea, const float* __restrict__ w1,
                        const float* __restrict__ b1, float* __restrict__ hrelu) {
    int idx = blockIdx.x * blockDim.x + threadIdx.x;
    if (idx >= cE * cH) return;
    int e = idx >> 7, j = idx & 127;
    float acc = b1[j];
    const float* er = ea + e * cEF;
#pragma unroll
    for (int i = 0; i < cEF; i++) acc += er[i] * w1[i * cH + j];
    hrelu[idx] = fmaxf(acc, 0.0f);
}
// Wcat [64][256] = [conv_root | gru_w_hh]; bcat [256] = [0 | gru_b_hh]
__global__ void k_prepW(const float* __restrict__ wroot, const float* __restrict__ whh,
                        const float* __restrict__ bhh,
                        float* __restrict__ Wcat, float* __restrict__ bcat) {
    int idx = blockIdx.x * blockDim.x + threadIdx.x;
    if (idx < cD * 4 * cD) {
        int k = idx >> 8, col = idx & 255;
        Wcat[idx] = (col < cD) ? wroot[k * cD + col] : whh[k * 3 * cD + (col - cD)];
    }
    if (idx < 4 * cD) bcat[idx] = (idx < cD) ? 0.0f : bhh[idx - cD];
}

// -------- TF32 tensor GEMM for ew: half C[E,4096] = A[E,128] @ B[128,4096] + bias --------
__global__ void __launch_bounds__(256) k_ewgemm(const float* __restrict__ A,
                                                const float* __restrict__ Bw,
                                                const float* __restrict__ bias,
                                                __half* __restrict__ C) {
    __shared__ uint32_t As[32][132];
    __shared__ uint32_t Bs[32][132];

    const int tid = threadIdx.x;
    const int warp = tid >> 5, lane = tid & 31;
    const int wm = warp >> 2, wn = warp & 3;
    const int g = lane >> 2, c = lane & 3;
    const int rowBase = blockIdx.y * 128;
    const int colBase = blockIdx.x * 128;

    float acc[4][4][4];
#pragma unroll
    for (int mt = 0; mt < 4; mt++)
#pragma unroll
        for (int nt = 0; nt < 4; nt++)
#pragma unroll
            for (int j = 0; j < 4; j++) acc[mt][nt][j] = 0.0f;

#pragma unroll
    for (int ck = 0; ck < 4; ck++) {
        const int k0 = ck * 32;
#pragma unroll
        for (int it = 0; it < 4; it++) {
            int idx = tid + it * 256;
            int row = idx >> 3, kq = idx & 7;
            int grow = rowBase + row;
            float4 v = make_float4(0.f, 0.f, 0.f, 0.f);
            if (grow < cE) v = *(const float4*)(A + (size_t)grow * cH + k0 + kq * 4);
            As[kq * 4 + 0][row] = f2tf32(v.x);
            As[kq * 4 + 1][row] = f2tf32(v.y);
            As[kq * 4 + 2][row] = f2tf32(v.z);
            As[kq * 4 + 3][row] = f2tf32(v.w);
        }
#pragma unroll
        for (int it = 0; it < 4; it++) {
            int idx = tid + it * 256;
            int kr = idx >> 5, nq = idx & 31;
            float4 v = *(const float4*)(Bw + (size_t)(k0 + kr) * cDSQ + colBase + nq * 4);
            uint4 u;
            u.x = f2tf32(v.x); u.y = f2tf32(v.y); u.z = f2tf32(v.z); u.w = f2tf32(v.w);
            *(uint4*)&Bs[kr][nq * 4] = u;
        }
        __syncthreads();

#pragma unroll
        for (int kk = 0; kk < 32; kk += 8) {
            uint32_t af[4][4];
#pragma unroll
            for (int mt = 0; mt < 4; mt++) {
                int r = wm * 64 + mt * 16 + g;
                af[mt][0] = As[kk + c][r];
                af[mt][1] = As[kk + c][r + 8];
                af[mt][2] = As[kk + c + 4][r];
                af[mt][3] = As[kk + c + 4][r + 8];
            }
            uint32_t bf[4][2];
#pragma unroll
            for (int nt = 0; nt < 4; nt++) {
                int n = wn * 32 + nt * 8 + g;
                bf[nt][0] = Bs[kk + c][n];
                bf[nt][1] = Bs[kk + c + 4][n];
            }
#pragma unroll
            for (int mt = 0; mt < 4; mt++)
#pragma unroll
                for (int nt = 0; nt < 4; nt++)
                    mma_tf32(acc[mt][nt], af[mt], bf[nt]);
        }
        __syncthreads();
    }

#pragma unroll
    for (int mt = 0; mt < 4; mt++) {
        int r0 = rowBase + wm * 64 + mt * 16 + g;
#pragma unroll
        for (int nt = 0; nt < 4; nt++) {
            int cc = colBase + wn * 32 + nt * 8 + c * 2;
            float b0 = bias[cc], b1 = bias[cc + 1];
            if (r0 < cE) {
                __half2 v = __floats2half2_rn(acc[mt][nt][0] + b0, acc[mt][nt][1] + b1);
                *(__half2*)(C + (size_t)r0 * cDSQ + cc) = v;
            }
            if (r0 + 8 < cE) {
                __half2 v = __floats2half2_rn(acc[mt][nt][2] + b0, acc[mt][nt][3] + b1);
                *(__half2*)(C + (size_t)(r0 + 8) * cDSQ + cc) = v;
            }
        }
    }
}

// -------- TF32 node GEMM: CTA 128m x 64n, K=64, dynamic smem (51200 B) --------
#define NG_SMEM (64 * 132 * 4 + 64 * 68 * 4)
__global__ void __launch_bounds__(128) k_nodegemm(int M, int ldb,
                                                  const float* __restrict__ A,
                                                  const float* __restrict__ Bw,
                                                  const float* __restrict__ bias,
                                                  float* __restrict__ Cp, int ldc) {
    extern __shared__ uint32_t ng_sm[];
    uint32_t (*As)[132] = (uint32_t (*)[132])ng_sm;              // [64][132]
    uint32_t (*Bs)[68]  = (uint32_t (*)[68])(ng_sm + 64 * 132);  // [64][68]

    const int tid = threadIdx.x;
    const int warp = tid >> 5, lane = tid & 31;
    const int g = lane >> 2, c = lane & 3;
    const int rowBase = blockIdx.y * 128;
    const int colBase = blockIdx.x * 64;

    // load A: thread t -> row t (128 rows, 64 k each)
    {
        int grow = rowBase + tid;
        if (grow < M) {
            const float4* ar = (const float4*)(A + (size_t)grow * cD);
#pragma unroll
            for (int q = 0; q < 16; q++) {
                float4 v = ar[q];
                As[q * 4 + 0][tid] = f2tf32(v.x);
                As[q * 4 + 1][tid] = f2tf32(v.y);
                As[q * 4 + 2][tid] = f2tf32(v.z);
                As[q * 4 + 3][tid] = f2tf32(v.w);
            }
        } else {
#pragma unroll
            for (int q = 0; q < 64; q++) As[q][tid] = 0u;
        }
    }
    // load B tile [64k][64n]
    {
        int kr = tid >> 1, half = tid & 1;
        const float4* br = (const float4*)(Bw + (size_t)kr * ldb + colBase + half * 32);
#pragma unroll
        for (int q = 0; q < 8; q++) {
            float4 v = br[q];
            int nq = half * 8 + q;
            uint4 u;
            u.x = f2tf32(v.x); u.y = f2tf32(v.y); u.z = f2tf32(v.z); u.w = f2tf32(v.w);
            *(uint4*)&Bs[kr][nq * 4] = u;
        }
    }
    __syncthreads();

    float acc[2][8][4];
#pragma unroll
    for (int mt = 0; mt < 2; mt++)
#pragma unroll
        for (int nt = 0; nt < 8; nt++)
#pragma unroll
            for (int j = 0; j < 4; j++) acc[mt][nt][j] = 0.0f;

    const int r0 = warp * 32;
#pragma unroll
    for (int k0 = 0; k0 < 64; k0 += 8) {
        uint32_t af[2][4];
#pragma unroll
        for (int mt = 0; mt < 2; mt++) {
            int r = r0 + mt * 16 + g;
            af[mt][0] = As[k0 + c][r];
            af[mt][1] = As[k0 + c][r + 8];
            af[mt][2] = As[k0 + c + 4][r];
            af[mt][3] = As[k0 + c + 4][r + 8];
        }
#pragma unroll
        for (int nt = 0; nt < 8; nt++) {
            uint32_t bf[2];
            bf[0] = Bs[k0 + c][nt * 8 + g];
            bf[1] = Bs[k0 + c + 4][nt * 8 + g];
            mma_tf32(acc[0][nt], af[0], bf);
            mma_tf32(acc[1][nt], af[1], bf);
        }
    }

#pragma unroll
    for (int mt = 0; mt < 2; mt++) {
        int rr0 = rowBase + r0 + mt * 16 + g;
        int rr1 = rr0 + 8;
#pragma unroll
        for (int nt = 0; nt < 8; nt++) {
            int cc = colBase + nt * 8 + c * 2;
            float b0 = bias ? bias[cc] : 0.0f;
            float b1 = bias ? bias[cc + 1] : 0.0f;
            if (rr0 < M) {
                float2 v = make_float2(acc[mt][nt][0] + b0, acc[mt][nt][1] + b1);
                *(float2*)(Cp + (size_t)rr0 * ldc + cc) = v;
            }
            if (rr1 < M) {
                float2 v = make_float2(acc[mt][nt][2] + b0, acc[mt][nt][3] + b1);
                *(float2*)(Cp + (size_t)rr1 * ldc + cc) = v;
            }
        }
    }
}

// -------- per-edge matvec + scatter with fp16 ew --------
__global__ void k_msg(const float* __restrict__ out, const __half* __restrict__ ew,
                      const int* __restrict__ src, const int* __restrict__ dst,
                      float* __restrict__ agg) {
    int e = blockIdx.x * blockDim.y + threadIdx.y;
    if (e >= cE) return;
    int lane = threadIdx.x;
    int s = src[e];
    const float* vo = out + (size_t)s * cD;
    const __half2* w = (const __half2*)(ew + (size_t)e * cDSQ);
    float a0 = 0.0f, a1 = 0.0f;
#pragma unroll 8
    for (int i = 0; i < cD; i++) {
        float v = __ldg(vo + i);
        float2 wp = __half22float2(w[i * 32 + lane]);
        a0 += v * wp.x;
        a1 += v * wp.y;
    }
    int dn = dst[e];
    atomicAdd(&agg[(size_t)dn * cD + 2 * lane], a0);
    atomicAdd(&agg[(size_t)dn * cD + 2 * lane + 1], a1);
}

// m = relu(agg/deg + CG[:,0:64] + conv_bias)
__global__ void k_m(const float* __restrict__ agg, const float* __restrict__ CG,
                    const float* __restrict__ deg, const float* __restrict__ cbias,
                    float* __restrict__ m) {
    int idx = blockIdx.x * blockDim.x + threadIdx.x;
    if (idx >= cN * cD) return;
    int n = idx >> 6, d = idx & 63;
    float dg = fmaxf(deg[n], 1.0f);
    float v = agg[idx] / dg + CG[(size_t)n * 4 * cD + d] + cbias[d];
    m[idx] = fmaxf(v, 0.0f);
}

// GRU gates: G1 [N,192]; G2 = CG[:,64:256]
__global__ void k_gate(const float* __restrict__ G1, const float* __restrict__ CG,
                       const float* __restrict__ h, float* __restrict__ hn) {
    int idx = blockIdx.x * blockDim.x + threadIdx.x;
    if (idx >= cN * cD) return;
    int n = idx >> 6, d = idx & 63;
    const float* g1 = G1 + (size_t)n * 3 * cD;
    const float* g2 = CG + (size_t)n * 4 * cD + cD;
    float r = sigm(g1[d] + g2[d]);
    float z = sigm(g1[cD + d] + g2[cD + d]);
    float nn = tanhf(g1[2 * cD + d] + r * g2[2 * cD + d]);
    hn[idx] = (1.0f - z) * nn + z * h[idx];
}

// ---------------- Set2Set ----------------
__global__ void k_s2s_init(float* qsA, float* hlA, float* clA) {
    int i = blockIdx.x * blockDim.x + threadIdx.x;
    if (i < cB * 2 * cD) qsA[i] = 0.0f;
    if (i < cB * cD) { hlA[i] = 0.0f; clA[i] = 0.0f; }
}
__global__ void k_lstm(const float* __restrict__ qs, const float* __restrict__ hl,
                       const float* __restrict__ cl,
                       const float* __restrict__ w_ih, const float* __restrict__ w_hh,
                       const float* __restrict__ b_ih, const float* __restrict__ b_hh,
                       float* __restrict__ hl_n, float* __restrict__ cl_n) {
    int idx = blockIdx.x * blockDim.x + threadIdx.x;
    if (idx >= cB * cD) return;
    int b = idx >> 6, d = idx & 63;
    float acc0 = b_ih[d] + b_hh[d];
    float acc1 = b_ih[cD + d] + b_hh[cD + d];
    float acc2 = b_ih[2 * cD + d] + b_hh[2 * cD + d];
    float acc3 = b_ih[3 * cD + d] + b_hh[3 * cD + d];
    const float* q = qs + b * 2 * cD;
#pragma unroll 4
    for (int k = 0; k < 2 * cD; k++) {
        float qv = q[k];
        const float* wr = w_ih + k * 4 * cD;
        acc0 += qv * wr[d]; acc1 += qv * wr[cD + d];
        acc2 += qv * wr[2 * cD + d]; acc3 += qv * wr[3 * cD + d];
    }
    const float* hr = hl + b * cD;
#pragma unroll 4
    for (int k = 0; k < cD; k++) {
        float hv = hr[k];
        const float* wr = w_hh + k * 4 * cD;
        acc0 += hv * wr[d]; acc1 += hv * wr[cD + d];
        acc2 += hv * wr[2 * cD + d]; acc3 += hv * wr[3 * cD + d];
    }
    float ig = sigm(acc0), fg = sigm(acc1), gg = tanhf(acc2), og = sigm(acc3);
    float cc2 = fg * cl[idx] + ig * gg;
    cl_n[idx] = cc2;
    hl_n[idx] = og * tanhf(cc2);
}
__global__ void k_zero_bat(unsigned* emaxu, float* esum, float* rvec) {
    int i = blockIdx.x * blockDim.x + threadIdx.x;
    if (i < cB) { emaxu[i] = 0u; esum[i] = 0.0f; }
    if (i < cB * cD) rvec[i] = 0.0f;
}
__global__ void k_attn1(const float* __restrict__ out, const int* __restrict__ batch,
                        const float* __restrict__ hl, float* __restrict__ esc,
                        unsigned* __restrict__ emaxu) {
    int n = blockIdx.x * blockDim.x + threadIdx.x;
    if (n >= cN) return;
    int b = batch[n];
    const float* o = out + (size_t)n * cD;
    const float* q = hl + (size_t)b * cD;
    float acc = 0.0f;
#pragma unroll 8
    for (int d = 0; d < cD; d++) acc += o[d] * q[d];
    esc[n] = acc;
    atomicMax(&emaxu[b], f2u(acc));
}
__global__ void k_attn2(const int* __restrict__ batch, float* __restrict__ esc,
                        const unsigned* __restrict__ emaxu, float* __restrict__ esum) {
    int n = blockIdx.x * blockDim.x + threadIdx.x;
    if (n >= cN) return;
    int b = batch[n];
    float ee = expf(esc[n] - u2f(emaxu[b]));
    esc[n] = ee;
    atomicAdd(&esum[b], ee);
}
__global__ void k_attn3(const float* __restrict__ out, const int* __restrict__ batch,
                        const float* __restrict__ esc, const float* __restrict__ esum,
                        float* __restrict__ rvec) {
    int idx = blockIdx.x * blockDim.x + threadIdx.x;
    if (idx >= cN * cD) return;
    int n = idx >> 6, d = idx & 63;
    int b = batch[n];
    float a = esc[n] / esum[b];
    atomicAdd(&rvec[(size_t)b * cD + d], a * out[idx]);
}
__global__ void k_qstar(const float* __restrict__ hl, const float* __restrict__ rvec,
                        float* __restrict__ qs_n) {
    int idx = blockIdx.x * blockDim.x + threadIdx.x;
    if (idx >= cB * 2 * cD) return;
    int b = idx >> 7, c = idx & 127;
    qs_n[idx] = (c < cD) ? hl[b * cD + c] : rvec[b * cD + (c - cD)];
}
__global__ void k_lin1(const float* __restrict__ qs, const float* __restrict__ w,
                       const float* __restrict__ b, float* __restrict__ out) {
    int idx = blockIdx.x * blockDim.x + threadIdx.x;
    if (idx >= cB * cD) return;
    int bb = idx >> 6, d = idx & 63;
    float acc = b[d];
    const float* q = qs + bb * 2 * cD;
#pragma unroll 8
    for (int k = 0; k < 2 * cD; k++) acc += q[k] * w[k * cD + d];
    out[idx] = fmaxf(acc, 0.0f);
}

// ---------------- launch ----------------
extern "C" void kernel_launch(void* const* d_in, const int* in_sizes, int n_in,
                              void* d_out, int out_size) {
    const float* x        = (const float*)d_in[0];
    const float* ea       = (const float*)d_in[1];
    const int*   ei       = (const int*)d_in[2];
    const int*   batch    = (const int*)d_in[3];
    const float* lin0_w   = (const float*)d_in[4];
    const float* lin0_b   = (const float*)d_in[5];
    const float* net_w1   = (const float*)d_in[6];
    const float* net_b1   = (const float*)d_in[7];
    const float* net_w2   = (const float*)d_in[8];
    const float* net_b2   = (const float*)d_in[9];
    const float* conv_root= (const float*)d_in[10];
    const float* conv_bias= (const float*)d_in[11];
    const float* gru_w_ih = (const float*)d_in[12];
    const float* gru_w_hh = (const float*)d_in[13];
    const float* gru_b_ih = (const float*)d_in[14];
    const float* gru_b_hh = (const float*)d_in[15];
    const float* lstm_w_ih= (const float*)d_in[16];
    const float* lstm_w_hh= (const float*)d_in[17];
    const float* lstm_b_ih= (const float*)d_in[18];
    const float* lstm_b_hh= (const float*)d_in[19];
    const float* lin1_w   = (const float*)d_in[20];
    const float* lin1_b   = (const float*)d_in[21];
    float* out = (float*)d_out;

    const int* src = ei;
    const int* dst = ei + cE;

    void* p;
    cudaGetSymbolAddress(&p, g_h0);    float* p_h0 = (float*)p;
    cudaGetSymbolAddress(&p, g_h1);    float* p_h1 = (float*)p;
    cudaGetSymbolAddress(&p, g_hrelu); float* p_hr = (float*)p;
    cudaGetSymbolAddress(&p, g_ewh);   __half* p_ewh = (__half*)p;
    cudaGetSymbolAddress(&p, g_agg);   float* p_agg = (float*)p;
    cudaGetSymbolAddress(&p, g_m);     float* p_m = (float*)p;
    cudaGetSymbolAddress(&p, g_CG);    float* p_CG = (float*)p;
    cudaGetSymbolAddress(&p, g_G1);    float* p_G1 = (float*)p;
    cudaGetSymbolAddress(&p, g_Wcat);  float* p_Wcat = (float*)p;
    cudaGetSymbolAddress(&p, g_bcat);  float* p_bcat = (float*)p;
    cudaGetSymbolAddress(&p, g_deg);   float* p_deg = (float*)p;
    cudaGetSymbolAddress(&p, g_esc);   float* p_esc = (float*)p;
    cudaGetSymbolAddress(&p, g_emaxu); unsigned* p_emax = (unsigned*)p;
    cudaGetSymbolAddress(&p, g_esum);  float* p_esum = (float*)p;
    cudaGetSymbolAddress(&p, g_rvec);  float* p_rvec = (float*)p;
    cudaGetSymbolAddress(&p, g_qsA);   float* p_qsA = (float*)p;
    cudaGetSymbolAddress(&p, g_qsB);   float* p_qsB = (float*)p;
    cudaGetSymbolAddress(&p, g_hlA);   float* p_hlA = (float*)p;
    cudaGetSymbolAddress(&p, g_hlB);   float* p_hlB = (float*)p;
    cudaGetSymbolAddress(&p, g_clA);   float* p_clA = (float*)p;
    cudaGetSymbolAddress(&p, g_clB);   float* p_clB = (float*)p;

    const int T = 256;
    cudaFuncSetAttribute(k_nodegemm, cudaFuncAttributeMaxDynamicSharedMemorySize, NG_SMEM);

    // degree
    k_deg_zero<<<(cN + T - 1) / T, T>>>(p_deg);
    k_deg<<<(cE + T - 1) / T, T>>>(dst, p_deg);

    // lin0 -> h0
    k_lin0<<<(cN * cD + T - 1) / T, T>>>(x, lin0_w, lin0_b, p_h0);

    // edge net + preps
    k_edge1<<<(cE * cH + T - 1) / T, T>>>(ea, net_w1, net_b1, p_hr);
    k_prepW<<<(cD * 4 * cD + T - 1) / T, T>>>(conv_root, gru_w_hh, gru_b_hh, p_Wcat, p_bcat);
    {
        dim3 grid(cDSQ / 128, (cE + 127) / 128);   // 32 x 313
        k_ewgemm<<<grid, 256>>>(p_hr, net_w2, net_b2, p_ewh);
    }

    // 3 message-passing steps
    for (int s = 0; s < 3; s++) {
        float* cur = (s & 1) ? p_h1 : p_h0;
        float* nxt = (s & 1) ? p_h0 : p_h1;

        k_zero<<<(cN * cD + T - 1) / T, T>>>(p_agg, cN * cD);
        {
            dim3 blk(32, 8);
            k_msg<<<(cE + 7) / 8, blk>>>(cur, p_ewh, src, dst, p_agg);
        }
        // CG = cur @ Wcat + bcat -> [croot | G2]
        {
            dim3 grid(4, (cN + 127) / 128);
            k_nodegemm<<<grid, 128, NG_SMEM>>>(cN, 4 * cD, cur, p_Wcat, p_bcat, p_CG, 4 * cD);
        }
        k_m<<<(cN * cD + T - 1) / T, T>>>(p_agg, p_CG, p_deg, conv_bias, p_m);
        // G1 = m @ gru_w_ih + b_ih
        {
            dim3 grid(3, (cN + 127) / 128);
            k_nodegemm<<<grid, 128, NG_SMEM>>>(cN, 3 * cD, p_m, gru_w_ih, gru_b_ih, p_G1, 3 * cD);
        }
        k_gate<<<(cN * cD + T - 1) / T, T>>>(p_G1, p_CG, cur, nxt);
    }
    float* p_hfin = p_h1;

    // Set2Set
    k_s2s_init<<<(cB * 2 * cD + T - 1) / T, T>>>(p_qsA, p_hlA, p_clA);
    for (int t = 0; t < 3; t++) {
        float* qs_c = (t & 1) ? p_qsB : p_qsA;
        float* qs_n = (t & 1) ? p_qsA : p_qsB;
        float* hl_c = (t & 1) ? p_hlB : p_hlA;
        float* hl_n = (t & 1) ? p_hlA : p_hlB;
        float* cl_c = (t & 1) ? p_clB : p_clA;
        float* cl_n = (t & 1) ? p_clA : p_clB;

        k_lstm<<<(cB * cD + T - 1) / T, T>>>(qs_c, hl_c, cl_c, lstm_w_ih, lstm_w_hh,
                                             lstm_b_ih, lstm_b_hh, hl_n, cl_n);
        k_zero_bat<<<(cB * cD + T - 1) / T, T>>>(p_emax, p_esum, p_rvec);
        k_attn1<<<(cN + T - 1) / T, T>>>(p_hfin, batch, hl_n, p_esc, p_emax);
        k_attn2<<<(cN + T - 1) / T, T>>>(batch, p_esc, p_emax, p_esum);
        k_attn3<<<(cN * cD + T - 1) / T, T>>>(p_hfin, batch, p_esc, p_esum, p_rvec);
        k_qstar<<<(cB * 2 * cD + T - 1) / T, T>>>(hl_n, p_rvec, qs_n);
    }

    k_lin1<<<(cB * cD + T - 1) / T, T>>>(p_qsB, lin1_w, lin1_b, out);
}

// round 7
// speedup vs baseline: 2.4612x; 1.1432x over previous
#include <cuda_runtime.h>
#include <cuda_fp16.h>
#include <math.h>
#include <stdint.h>

// ---------------- problem constants ----------------
#define cN 10000
#define cE 40000
#define cD 64
#define cB 512
#define cFIN 11
#define cEF 5
#define cH 128
#define cDSQ 4096

// ---------------- device scratch ----------------
__device__ float g_h0[cN * cD];
__device__ float g_h1[cN * cD];
__device__ float g_hrelu[cE * cH];            // 20 MB
__device__ __half g_ewh[(size_t)cE * cDSQ];   // 320 MB fp16 edge weights (bias folded in)
__device__ float g_agg[cN * cD];
__device__ float g_CG[cN * 4 * cD];           // [N,256] = [croot | G2]
__device__ float g_G1[cN * 3 * cD];
__device__ float g_Wcat[cD * 4 * cD];         // [64,256] = [conv_root | gru_w_hh]
__device__ float g_bcat[4 * cD];
__device__ float g_deg[cN];

// ---------------- helpers ----------------
__device__ __forceinline__ float sigm(float x) { return 1.0f / (1.0f + expf(-x)); }

__device__ __forceinline__ uint32_t f2tf32(float f) {
    uint32_t u;
    asm("cvt.rna.tf32.f32 %0, %1;" : "=r"(u) : "f"(f));
    return u;
}
__device__ __forceinline__ void mma_tf32(float* d, const uint32_t* a, const uint32_t* b) {
    asm volatile(
        "mma.sync.aligned.m16n8k8.row.col.f32.tf32.tf32.f32 "
        "{%0,%1,%2,%3}, {%4,%5,%6,%7}, {%8,%9}, {%0,%1,%2,%3};"
        : "+f"(d[0]), "+f"(d[1]), "+f"(d[2]), "+f"(d[3])
        : "r"(a[0]), "r"(a[1]), "r"(a[2]), "r"(a[3]), "r"(b[0]), "r"(b[1]));
}

// ---------------- small kernels ----------------
__global__ void k_zero(float* p, int n) {
    int i = blockIdx.x * blockDim.x + threadIdx.x;
    if (i < n) p[i] = 0.0f;
}
__global__ void k_deg_zero(float* deg) {
    int i = blockIdx.x * blockDim.x + threadIdx.x;
    if (i < cN) deg[i] = 0.0f;
}
__global__ void k_deg(const int* __restrict__ dst, float* deg) {
    int e = blockIdx.x * blockDim.x + threadIdx.x;
    if (e < cE) atomicAdd(&deg[dst[e]], 1.0f);
}
__global__ void k_lin0(const float* __restrict__ x, const float* __restrict__ w,
                       const float* __restrict__ b, float* __restrict__ h0) {
    int idx = blockIdx.x * blockDim.x + threadIdx.x;
    if (idx >= cN * cD) return;
    int n = idx >> 6, d = idx & 63;
    float acc = b[d];
    const float* xr = x + n * cFIN;
#pragma unroll
    for (int i = 0; i < cFIN; i++) acc += xr[i] * w[i * cD + d];
    h0[idx] = fmaxf(acc, 0.0f);
}
__global__ void k_edge1(const float* __restrict__ ea, const float* __restrict__ w1,
                        const float* __restrict__ b1, float* __restrict__ hrelu) {
    int idx = blockIdx.x * blockDim.x + threadIdx.x;
    if (idx >= cE * cH) return;
    int e = idx >> 7, j = idx & 127;
    float acc = b1[j];
    const float* er = ea + e * cEF;
#pragma unroll
    for (int i = 0; i < cEF; i++) acc += er[i] * w1[i * cH + j];
    hrelu[idx] = fmaxf(acc, 0.0f);
}
// Wcat [64][256] = [conv_root | gru_w_hh]; bcat [256] = [0 | gru_b_hh]
__global__ void k_prepW(const float* __restrict__ wroot, const float* __restrict__ whh,
                        const float* __restrict__ bhh,
                        float* __restrict__ Wcat, float* __restrict__ bcat) {
    int idx = blockIdx.x * blockDim.x + threadIdx.x;
    if (idx < cD * 4 * cD) {
        int k = idx >> 8, col = idx & 255;
        Wcat[idx] = (col < cD) ? wroot[k * cD + col] : whh[k * 3 * cD + (col - cD)];
    }
    if (idx < 4 * cD) bcat[idx] = (idx < cD) ? 0.0f : bhh[idx - cD];
}

// -------- TF32 tensor GEMM for ew: half C[E,4096] = A[E,128] @ B[128,4096] + bias --------
__global__ void __launch_bounds__(256) k_ewgemm(const float* __restrict__ A,
                                                const float* __restrict__ Bw,
                                                const float* __restrict__ bias,
                                                __half* __restrict__ C) {
    __shared__ uint32_t As[32][132];
    __shared__ uint32_t Bs[32][132];

    const int tid = threadIdx.x;
    const int warp = tid >> 5, lane = tid & 31;
    const int wm = warp >> 2, wn = warp & 3;
    const int g = lane >> 2, c = lane & 3;
    const int rowBase = blockIdx.y * 128;
    const int colBase = blockIdx.x * 128;

    float acc[4][4][4];
#pragma unroll
    for (int mt = 0; mt < 4; mt++)
#pragma unroll
        for (int nt = 0; nt < 4; nt++)
#pragma unroll
            for (int j = 0; j < 4; j++) acc[mt][nt][j] = 0.0f;

#pragma unroll
    for (int ck = 0; ck < 4; ck++) {
        const int k0 = ck * 32;
#pragma unroll
        for (int it = 0; it < 4; it++) {
            int idx = tid + it * 256;
            int row = idx >> 3, kq = idx & 7;
            int grow = rowBase + row;
            float4 v = make_float4(0.f, 0.f, 0.f, 0.f);
            if (grow < cE) v = *(const float4*)(A + (size_t)grow * cH + k0 + kq * 4);
            As[kq * 4 + 0][row] = f2tf32(v.x);
            As[kq * 4 + 1][row] = f2tf32(v.y);
            As[kq * 4 + 2][row] = f2tf32(v.z);
            As[kq * 4 + 3][row] = f2tf32(v.w);
        }
#pragma unroll
        for (int it = 0; it < 4; it++) {
            int idx = tid + it * 256;
            int kr = idx >> 5, nq = idx & 31;
            float4 v = *(const float4*)(Bw + (size_t)(k0 + kr) * cDSQ + colBase + nq * 4);
            uint4 u;
            u.x = f2tf32(v.x); u.y = f2tf32(v.y); u.z = f2tf32(v.z); u.w = f2tf32(v.w);
            *(uint4*)&Bs[kr][nq * 4] = u;
        }
        __syncthreads();

#pragma unroll
        for (int kk = 0; kk < 32; kk += 8) {
            uint32_t af[4][4];
#pragma unroll
            for (int mt = 0; mt < 4; mt++) {
                int r = wm * 64 + mt * 16 + g;
                af[mt][0] = As[kk + c][r];
                af[mt][1] = As[kk + c][r + 8];
                af[mt][2] = As[kk + c + 4][r];
                af[mt][3] = As[kk + c + 4][r + 8];
            }
            uint32_t bf[4][2];
#pragma unroll
            for (int nt = 0; nt < 4; nt++) {
                int n = wn * 32 + nt * 8 + g;
                bf[nt][0] = Bs[kk + c][n];
                bf[nt][1] = Bs[kk + c + 4][n];
            }
#pragma unroll
            for (int mt = 0; mt < 4; mt++)
#pragma unroll
                for (int nt = 0; nt < 4; nt++)
                    mma_tf32(acc[mt][nt], af[mt], bf[nt]);
        }
        __syncthreads();
    }

#pragma unroll
    for (int mt = 0; mt < 4; mt++) {
        int r0 = rowBase + wm * 64 + mt * 16 + g;
#pragma unroll
        for (int nt = 0; nt < 4; nt++) {
            int cc = colBase + wn * 32 + nt * 8 + c * 2;
            float b0 = bias[cc], b1 = bias[cc + 1];
            if (r0 < cE) {
                __half2 v = __floats2half2_rn(acc[mt][nt][0] + b0, acc[mt][nt][1] + b1);
                *(__half2*)(C + (size_t)r0 * cDSQ + cc) = v;
            }
            if (r0 + 8 < cE) {
                __half2 v = __floats2half2_rn(acc[mt][nt][2] + b0, acc[mt][nt][3] + b1);
                *(__half2*)(C + (size_t)(r0 + 8) * cDSQ + cc) = v;
            }
        }
    }
}

// -------- TF32 node GEMM core (shared by plain and fused-m variants) --------
#define NG_SMEM (64 * 132 * 4 + 64 * 68 * 4)

__device__ __forceinline__ void nodegemm_core(
    uint32_t (*As)[132], uint32_t (*Bs)[68],
    int M, int ldb, const float* __restrict__ Bw,
    const float* __restrict__ bias, float* __restrict__ Cp, int ldc,
    int rowBase, int colBase)
{
    const int tid = threadIdx.x;
    const int warp = tid >> 5, lane = tid & 31;
    const int g = lane >> 2, c = lane & 3;

    // load B tile [64k][64n]
    {
        int kr = tid >> 1, half = tid & 1;
        const float4* br = (const float4*)(Bw + (size_t)kr * ldb + colBase + half * 32);
#pragma unroll
        for (int q = 0; q < 8; q++) {
            float4 v = br[q];
            int nq = half * 8 + q;
            uint4 u;
            u.x = f2tf32(v.x); u.y = f2tf32(v.y); u.z = f2tf32(v.z); u.w = f2tf32(v.w);
            *(uint4*)&Bs[kr][nq * 4] = u;
        }
    }
    __syncthreads();

    float acc[2][8][4];
#pragma unroll
    for (int mt = 0; mt < 2; mt++)
#pragma unroll
        for (int nt = 0; nt < 8; nt++)
#pragma unroll
            for (int j = 0; j < 4; j++) acc[mt][nt][j] = 0.0f;

    const int r0 = warp * 32;
#pragma unroll
    for (int k0 = 0; k0 < 64; k0 += 8) {
        uint32_t af[2][4];
#pragma unroll
        for (int mt = 0; mt < 2; mt++) {
            int r = r0 + mt * 16 + g;
            af[mt][0] = As[k0 + c][r];
            af[mt][1] = As[k0 + c][r + 8];
            af[mt][2] = As[k0 + c + 4][r];
            af[mt][3] = As[k0 + c + 4][r + 8];
        }
#pragma unroll
        for (int nt = 0; nt < 8; nt++) {
            uint32_t bf[2];
            bf[0] = Bs[k0 + c][nt * 8 + g];
            bf[1] = Bs[k0 + c + 4][nt * 8 + g];
            mma_tf32(acc[0][nt], af[0], bf);
            mma_tf32(acc[1][nt], af[1], bf);
        }
    }

#pragma unroll
    for (int mt = 0; mt < 2; mt++) {
        int rr0 = rowBase + r0 + mt * 16 + g;
        int rr1 = rr0 + 8;
#pragma unroll
        for (int nt = 0; nt < 8; nt++) {
            int cc = colBase + nt * 8 + c * 2;
            float b0 = bias ? bias[cc] : 0.0f;
            float b1 = bias ? bias[cc + 1] : 0.0f;
            if (rr0 < M) {
                float2 v = make_float2(acc[mt][nt][0] + b0, acc[mt][nt][1] + b1);
                *(float2*)(Cp + (size_t)rr0 * ldc + cc) = v;
            }
            if (rr1 < M) {
                float2 v = make_float2(acc[mt][nt][2] + b0, acc[mt][nt][3] + b1);
                *(float2*)(Cp + (size_t)rr1 * ldc + cc) = v;
            }
        }
    }
}

// plain node GEMM: A = dense [M,64] fp32
__global__ void __launch_bounds__(128) k_nodegemm(int M, int ldb,
                                                  const float* __restrict__ A,
                                                  const float* __restrict__ Bw,
                                                  const float* __restrict__ bias,
                                                  float* __restrict__ Cp, int ldc) {
    extern __shared__ uint32_t ng_sm[];
    uint32_t (*As)[132] = (uint32_t (*)[132])ng_sm;
    uint32_t (*Bs)[68]  = (uint32_t (*)[68])(ng_sm + 64 * 132);
    const int tid = threadIdx.x;
    const int rowBase = blockIdx.y * 128;
    {
        int grow = rowBase + tid;
        if (grow < M) {
            const float4* ar = (const float4*)(A + (size_t)grow * cD);
#pragma unroll
            for (int q = 0; q < 16; q++) {
                float4 v = ar[q];
                As[q * 4 + 0][tid] = f2tf32(v.x);
                As[q * 4 + 1][tid] = f2tf32(v.y);
                As[q * 4 + 2][tid] = f2tf32(v.z);
                As[q * 4 + 3][tid] = f2tf32(v.w);
            }
        } else {
#pragma unroll
            for (int q = 0; q < 64; q++) As[q][tid] = 0u;
        }
    }
    nodegemm_core(As, Bs, M, ldb, Bw, bias, Cp, ldc, rowBase, blockIdx.x * 64);
}

// fused-m node GEMM: A row = relu(agg/deg + CG[:,0:64] + cbias), for G1 = m @ gru_w_ih
__global__ void __launch_bounds__(128) k_mgemm(int M, int ldb,
                                               const float* __restrict__ agg,
                                               const float* __restrict__ CG,
                                               const float* __restrict__ deg,
                                               const float* __restrict__ cbias,
                                               const float* __restrict__ Bw,
                                               const float* __restrict__ bias,
                                               float* __restrict__ Cp, int ldc) {
    extern __shared__ uint32_t ng_sm[];
    uint32_t (*As)[132] = (uint32_t (*)[132])ng_sm;
    uint32_t (*Bs)[68]  = (uint32_t (*)[68])(ng_sm + 64 * 132);
    const int tid = threadIdx.x;
    const int rowBase = blockIdx.y * 128;
    {
        int grow = rowBase + tid;
        if (grow < M) {
            float inv = 1.0f / fmaxf(deg[grow], 1.0f);
            const float4* ag = (const float4*)(agg + (size_t)grow * cD);
            const float4* cg = (const float4*)(CG + (size_t)grow * 4 * cD);
            const float4* cb = (const float4*)(cbias);
#pragma unroll
            for (int q = 0; q < 16; q++) {
                float4 a = ag[q], cr = cg[q], bb = cb[q];
                As[q * 4 + 0][tid] = f2tf32(fmaxf(a.x * inv + cr.x + bb.x, 0.0f));
                As[q * 4 + 1][tid] = f2tf32(fmaxf(a.y * inv + cr.y + bb.y, 0.0f));
                As[q * 4 + 2][tid] = f2tf32(fmaxf(a.z * inv + cr.z + bb.z, 0.0f));
                As[q * 4 + 3][tid] = f2tf32(fmaxf(a.w * inv + cr.w + bb.w, 0.0f));
            }
        } else {
#pragma unroll
            for (int q = 0; q < 64; q++) As[q][tid] = 0u;
        }
    }
    nodegemm_core(As, Bs, M, ldb, Bw, bias, Cp, ldc, rowBase, blockIdx.x * 64);
}

// -------- per-edge matvec + scatter, vectorized 16B loads --------
// warp per edge; lane l: rows j*4+(l>>3), cols (l&7)*8..+7; butterfly reduce; 2 atomics/lane
__global__ void k_msg(const float* __restrict__ out, const __half* __restrict__ ew,
                      const int* __restrict__ src, const int* __restrict__ dst,
                      float* __restrict__ agg) {
    int e = blockIdx.x * blockDim.y + threadIdx.y;
    if (e >= cE) return;
    int lane = threadIdx.x;
    int s = src[e];
    float v_lo = __ldg(out + (size_t)s * cD + lane);
    float v_hi = __ldg(out + (size_t)s * cD + 32 + lane);
    const uint4* w = (const uint4*)(ew + (size_t)e * cDSQ);
    const int rl = lane >> 3, cl8 = lane & 7;
    float acc[8];
#pragma unroll
    for (int q = 0; q < 8; q++) acc[q] = 0.0f;

#pragma unroll
    for (int j = 0; j < 16; j++) {
        int row = j * 4 + rl;
        float side = (j < 8) ? v_lo : v_hi;
        float v = __shfl_sync(0xffffffffu, side, row & 31);
        uint4 u = w[row * 8 + cl8];
        __half2* h2 = (__half2*)&u;
#pragma unroll
        for (int q = 0; q < 4; q++) {
            float2 f = __half22float2(h2[q]);
            acc[q * 2]     += v * f.x;
            acc[q * 2 + 1] += v * f.y;
        }
    }
    // reduce across lanes xor 8, 16 (4 lanes share the same 8 cols)
#pragma unroll
    for (int off = 8; off <= 16; off <<= 1)
#pragma unroll
        for (int q = 0; q < 8; q++)
            acc[q] += __shfl_xor_sync(0xffffffffu, acc[q], off);

    int dn = dst[e];
    int col = cl8 * 8 + rl * 2;
    atomicAdd(&agg[(size_t)dn * cD + col],     acc[rl * 2]);
    atomicAdd(&agg[(size_t)dn * cD + col + 1], acc[rl * 2 + 1]);
}

// GRU gates: G1 [N,192]; G2 = CG[:,64:256]
__global__ void k_gate(const float* __restrict__ G1, const float* __restrict__ CG,
                       const float* __restrict__ h, float* __restrict__ hn) {
    int idx = blockIdx.x * blockDim.x + threadIdx.x;
    if (idx >= cN * cD) return;
    int n = idx >> 6, d = idx & 63;
    const float* g1 = G1 + (size_t)n * 3 * cD;
    const float* g2 = CG + (size_t)n * 4 * cD + cD;
    float r = sigm(g1[d] + g2[d]);
    float z = sigm(g1[cD + d] + g2[cD + d]);
    float nn = tanhf(g1[2 * cD + d] + r * g2[2 * cD + d]);
    hn[idx] = (1.0f - z) * nn + z * h[idx];
}

// -------- fused Set2Set (3 iterations) + final lin1: one block per graph --------
__global__ void __launch_bounds__(128) k_set2set(
    const float* __restrict__ hfin, const int* __restrict__ batch,
    const float* __restrict__ w_ih, const float* __restrict__ w_hh,
    const float* __restrict__ b_ih, const float* __restrict__ b_hh,
    const float* __restrict__ l1w, const float* __restrict__ l1b,
    float* __restrict__ outp)
{
    const int b = blockIdx.x;
    const int tid = threadIdx.x, warp = tid >> 5, lane = tid & 31;
    __shared__ float s_qstar[128], s_g[256], s_q[64], s_cl[64], s_rvec[64];
    __shared__ float s_wmax[4], s_wsum[4];
    __shared__ float s_gmax, s_gsum;
    __shared__ int s_s, s_e;

    if (tid == 0) {
        int lo = 0, hi = cN;
        while (lo < hi) { int mid = (lo + hi) >> 1; if (batch[mid] < b) lo = mid + 1; else hi = mid; }
        s_s = lo;
        hi = cN;
        while (lo < hi) { int mid = (lo + hi) >> 1; if (batch[mid] < b + 1) lo = mid + 1; else hi = mid; }
        s_e = lo;
    }
    s_qstar[tid] = 0.0f;
    if (tid < 64) { s_q[tid] = 0.0f; s_cl[tid] = 0.0f; }
    __syncthreads();

    for (int t = 0; t < 3; t++) {
        // LSTM: g[256] = qstar @ w_ih + b_ih + q(hl) @ w_hh + b_hh ; 2 cols/thread
        float g0 = b_ih[tid] + b_hh[tid];
        float g1 = b_ih[tid + 128] + b_hh[tid + 128];
#pragma unroll 4
        for (int k = 0; k < 128; k++) {
            float qv = s_qstar[k];
            g0 += qv * w_ih[k * 256 + tid];
            g1 += qv * w_ih[k * 256 + tid + 128];
        }
#pragma unroll 4
        for (int k = 0; k < 64; k++) {
            float hv = s_q[k];
            g0 += hv * w_hh[k * 256 + tid];
            g1 += hv * w_hh[k * 256 + tid + 128];
        }
        s_g[tid] = g0; s_g[tid + 128] = g1;
        __syncthreads();
        if (tid < 64) {
            float ig = sigm(s_g[tid]), fg = sigm(s_g[64 + tid]);
            float gg = tanhf(s_g[128 + tid]), og = sigm(s_g[192 + tid]);
            float c = fg * s_cl[tid] + ig * gg;
            s_cl[tid] = c;
            s_q[tid] = og * tanhf(c);
            s_rvec[tid] = 0.0f;
        }
        __syncthreads();

        const int ns = s_s, ne = s_e;
        // pass A: segment max of e_n = out[n] . q
        float wmax = -1e30f;
        for (int n = ns + warp; n < ne; n += 4) {
            const float* o = hfin + (size_t)n * cD;
            float d = o[lane] * s_q[lane] + o[32 + lane] * s_q[32 + lane];
#pragma unroll
            for (int off = 16; off; off >>= 1) d += __shfl_xor_sync(0xffffffffu, d, off);
            wmax = fmaxf(wmax, d);
        }
        if (lane == 0) s_wmax[warp] = wmax;
        __syncthreads();
        if (tid == 0)
            s_gmax = fmaxf(fmaxf(s_wmax[0], s_wmax[1]), fmaxf(s_wmax[2], s_wmax[3]));
        __syncthreads();
        const float gmax = s_gmax;

        // pass B: exp-sum and weighted node sum
        float wsum = 0.0f, rv0 = 0.0f, rv1 = 0.0f;
        for (int n = ns + warp; n < ne; n += 4) {
            const float* o = hfin + (size_t)n * cD;
            float d = o[lane] * s_q[lane] + o[32 + lane] * s_q[32 + lane];
#pragma unroll
            for (int off = 16; off; off >>= 1) d += __shfl_xor_sync(0xffffffffu, d, off);
            float ee = expf(d - gmax);
            wsum += ee;
            rv0 += ee * o[lane];
            rv1 += ee * o[32 + lane];
        }
        if (lane == 0) s_wsum[warp] = wsum;
        atomicAdd(&s_rvec[lane], rv0);
        atomicAdd(&s_rvec[32 + lane], rv1);
        __syncthreads();
        if (tid == 0) s_gsum = s_wsum[0] + s_wsum[1] + s_wsum[2] + s_wsum[3];
        __syncthreads();

        if (tid < 64) s_qstar[tid] = s_q[tid];
        else {
            float denom = s_gsum;
            s_qstar[tid] = (denom > 0.0f) ? s_rvec[tid - 64] / denom : 0.0f;
        }
        __syncthreads();
    }

    // lin1: out[b] = relu(qstar @ l1w + l1b)
    if (tid < 64) {
        float acc = l1b[tid];
#pragma unroll 4
        for (int k = 0; k < 128; k++) acc += s_qstar[k] * l1w[k * cD + tid];
        outp[b * cD + tid] = fmaxf(acc, 0.0f);
    }
}

// ---------------- launch ----------------
extern "C" void kernel_launch(void* const* d_in, const int* in_sizes, int n_in,
                              void* d_out, int out_size) {
    const float* x        = (const float*)d_in[0];
    const float* ea       = (const float*)d_in[1];
    const int*   ei       = (const int*)d_in[2];
    const int*   batch    = (const int*)d_in[3];
    const float* lin0_w   = (const float*)d_in[4];
    const float* lin0_b   = (const float*)d_in[5];
    const float* net_w1   = (const float*)d_in[6];
    const float* net_b1   = (const float*)d_in[7];
    const float* net_w2   = (const float*)d_in[8];
    const float* net_b2   = (const float*)d_in[9];
    const float* conv_root= (const float*)d_in[10];
    const float* conv_bias= (const float*)d_in[11];
    const float* gru_w_ih = (const float*)d_in[12];
    const float* gru_w_hh = (const float*)d_in[13];
    const float* gru_b_ih = (const float*)d_in[14];
    const float* gru_b_hh = (const float*)d_in[15];
    const float* lstm_w_ih= (const float*)d_in[16];
    const float* lstm_w_hh= (const float*)d_in[17];
    const float* lstm_b_ih= (const float*)d_in[18];
    const float* lstm_b_hh= (const float*)d_in[19];
    const float* lin1_w   = (const float*)d_in[20];
    const float* lin1_b   = (const float*)d_in[21];
    float* out = (float*)d_out;

    const int* src = ei;
    const int* dst = ei + cE;

    void* p;
    cudaGetSymbolAddress(&p, g_h0);    float* p_h0 = (float*)p;
    cudaGetSymbolAddress(&p, g_h1);    float* p_h1 = (float*)p;
    cudaGetSymbolAddress(&p, g_hrelu); float* p_hr = (float*)p;
    cudaGetSymbolAddress(&p, g_ewh);   __half* p_ewh = (__half*)p;
    cudaGetSymbolAddress(&p, g_agg);   float* p_agg = (float*)p;
    cudaGetSymbolAddress(&p, g_CG);    float* p_CG = (float*)p;
    cudaGetSymbolAddress(&p, g_G1);    float* p_G1 = (float*)p;
    cudaGetSymbolAddress(&p, g_Wcat);  float* p_Wcat = (float*)p;
    cudaGetSymbolAddress(&p, g_bcat);  float* p_bcat = (float*)p;
    cudaGetSymbolAddress(&p, g_deg);   float* p_deg = (float*)p;

    const int T = 256;
    cudaFuncSetAttribute(k_nodegemm, cudaFuncAttributeMaxDynamicSharedMemorySize, NG_SMEM);
    cudaFuncSetAttribute(k_mgemm, cudaFuncAttributeMaxDynamicSharedMemorySize, NG_SMEM);

    // degree
    k_deg_zero<<<(cN + T - 1) / T, T>>>(p_deg);
    k_deg<<<(cE + T - 1) / T, T>>>(dst, p_deg);

    // lin0 -> h0
    k_lin0<<<(cN * cD + T - 1) / T, T>>>(x, lin0_w, lin0_b, p_h0);

    // edge net + preps
    k_edge1<<<(cE * cH + T - 1) / T, T>>>(ea, net_w1, net_b1, p_hr);
    k_prepW<<<(cD * 4 * cD + T - 1) / T, T>>>(conv_root, gru_w_hh, gru_b_hh, p_Wcat, p_bcat);
    {
        dim3 grid(cDSQ / 128, (cE + 127) / 128);   // 32 x 313
        k_ewgemm<<<grid, 256>>>(p_hr, net_w2, net_b2, p_ewh);
    }

    // 3 message-passing steps
    for (int s = 0; s < 3; s++) {
        float* cur = (s & 1) ? p_h1 : p_h0;
        float* nxt = (s & 1) ? p_h0 : p_h1;

        k_zero<<<(cN * cD + T - 1) / T, T>>>(p_agg, cN * cD);
        {
            dim3 blk(32, 8);
            k_msg<<<(cE + 7) / 8, blk>>>(cur, p_ewh, src, dst, p_agg);
        }
        // CG = cur @ Wcat + bcat -> [croot | G2]
        {
            dim3 grid(4, (cN + 127) / 128);
            k_nodegemm<<<grid, 128, NG_SMEM>>>(cN, 4 * cD, cur, p_Wcat, p_bcat, p_CG, 4 * cD);
        }
        // G1 = relu(agg/deg + croot + cbias) @ gru_w_ih + b_ih   (m fused into A-load)
        {
            dim3 grid(3, (cN + 127) / 128);
            k_mgemm<<<grid, 128, NG_SMEM>>>(cN, 3 * cD, p_agg, p_CG, p_deg, conv_bias,
                                            gru_w_ih, gru_b_ih, p_G1, 3 * cD);
        }
        k_gate<<<(cN * cD + T - 1) / T, T>>>(p_G1, p_CG, cur, nxt);
    }
    float* p_hfin = p_h1;

    // fused Set2Set (3 iterations) + lin1
    k_set2set<<<cB, 128>>>(p_hfin, batch, lstm_w_ih, lstm_w_hh, lstm_b_ih, lstm_b_hh,
                           lin1_w, lin1_b, out);
}

// round 8
// speedup vs baseline: 3.9007x; 1.5849x over previous
#include <cuda_runtime.h>
#include <cuda_fp16.h>
#include <math.h>
#include <stdint.h>

// ---------------- problem constants ----------------
#define cN 10000
#define cE 40000
#define cD 64
#define cB 512
#define cFIN 11
#define cEF 5
#define cH 128
#define cDSQ 4096

// ---------------- device scratch ----------------
__device__ float g_h0[cN * cD];
__device__ float g_h1[cN * cD];
__device__ __half g_hreluh[cE * cH];          // 10 MB fp16 edge-net hidden
__device__ __half g_w2T[cDSQ * cH];           // 1 MB fp16 transposed [n][k]
__device__ __half g_ewh[(size_t)cE * cDSQ];   // 320 MB fp16 edge weights (bias folded in)
__device__ float g_agg[cN * cD];
__device__ float g_CG[cN * 4 * cD];           // [N,256] = [croot | G2]
__device__ float g_G1[cN * 3 * cD];
__device__ float g_Wcat[cD * 4 * cD];         // [64,256] = [conv_root | gru_w_hh]
__device__ float g_bcat[4 * cD];
__device__ float g_deg[cN];

// ---------------- helpers ----------------
__device__ __forceinline__ float sigm(float x) { return 1.0f / (1.0f + expf(-x)); }

__device__ __forceinline__ uint32_t f2tf32(float f) {
    uint32_t u;
    asm("cvt.rna.tf32.f32 %0, %1;" : "=r"(u) : "f"(f));
    return u;
}
__device__ __forceinline__ void mma_tf32(float* d, const uint32_t* a, const uint32_t* b) {
    asm volatile(
        "mma.sync.aligned.m16n8k8.row.col.f32.tf32.tf32.f32 "
        "{%0,%1,%2,%3}, {%4,%5,%6,%7}, {%8,%9}, {%0,%1,%2,%3};"
        : "+f"(d[0]), "+f"(d[1]), "+f"(d[2]), "+f"(d[3])
        : "r"(a[0]), "r"(a[1]), "r"(a[2]), "r"(a[3]), "r"(b[0]), "r"(b[1]));
}
__device__ __forceinline__ void mma_f16(float* d, const uint32_t* a, const uint32_t* b) {
    asm volatile(
        "mma.sync.aligned.m16n8k16.row.col.f32.f16.f16.f32 "
        "{%0,%1,%2,%3}, {%4,%5,%6,%7}, {%8,%9}, {%0,%1,%2,%3};"
        : "+f"(d[0]), "+f"(d[1]), "+f"(d[2]), "+f"(d[3])
        : "r"(a[0]), "r"(a[1]), "r"(a[2]), "r"(a[3]), "r"(b[0]), "r"(b[1]));
}
__device__ __forceinline__ void cp16(void* smem, const void* gmem) {
    uint32_t s = (uint32_t)__cvta_generic_to_shared(smem);
    asm volatile("cp.async.ca.shared.global [%0], [%1], 16;" :: "r"(s), "l"(gmem));
}

// ---------------- small kernels ----------------
__global__ void k_deg_zero(float* deg) {
    int i = blockIdx.x * blockDim.x + threadIdx.x;
    if (i < cN) deg[i] = 0.0f;
}
__global__ void k_deg(const int* __restrict__ dst, float* deg) {
    int e = blockIdx.x * blockDim.x + threadIdx.x;
    if (e < cE) atomicAdd(&deg[dst[e]], 1.0f);
}
// lin0 -> h0; also zero agg for step 0
__global__ void k_lin0(const float* __restrict__ x, const float* __restrict__ w,
                       const float* __restrict__ b, float* __restrict__ h0,
                       float* __restrict__ agg) {
    int idx = blockIdx.x * blockDim.x + threadIdx.x;
    if (idx >= cN * cD) return;
    int n = idx >> 6, d = idx & 63;
    float acc = b[d];
    const float* xr = x + n * cFIN;
#pragma unroll
    for (int i = 0; i < cFIN; i++) acc += xr[i] * w[i * cD + d];
    h0[idx] = fmaxf(acc, 0.0f);
    agg[idx] = 0.0f;
}
// edge-net layer 1, fp16 output
__global__ void k_edge1(const float* __restrict__ ea, const float* __restrict__ w1,
                        const float* __restrict__ b1, __half* __restrict__ hrelu) {
    int idx = blockIdx.x * blockDim.x + threadIdx.x;
    if (idx >= cE * cH) return;
    int e = idx >> 7, j = idx & 127;
    float acc = b1[j];
    const float* er = ea + e * cEF;
#pragma unroll
    for (int i = 0; i < cEF; i++) acc += er[i] * w1[i * cH + j];
    hrelu[idx] = __float2half(fmaxf(acc, 0.0f));
}
// w2T[n][k] = half(w2[k][n])
__global__ void k_prepB(const float* __restrict__ w2, __half* __restrict__ BT) {
    int idx = blockIdx.x * blockDim.x + threadIdx.x;
    if (idx >= cH * cDSQ) return;
    int n = idx >> 7, k = idx & 127;
    BT[idx] = __float2half(w2[(size_t)k * cDSQ + n]);
}
// Wcat [64][256] = [conv_root | gru_w_hh]; bcat [256] = [0 | gru_b_hh]
__global__ void k_prepW(const float* __restrict__ wroot, const float* __restrict__ whh,
                        const float* __restrict__ bhh,
                        float* __restrict__ Wcat, float* __restrict__ bcat) {
    int idx = blockIdx.x * blockDim.x + threadIdx.x;
    if (idx < cD * 4 * cD) {
        int k = idx >> 8, col = idx & 255;
        Wcat[idx] = (col < cD) ? wroot[k * cD + col] : whh[k * 3 * cD + (col - cD)];
    }
    if (idx < 4 * cD) bcat[idx] = (idx < cD) ? 0.0f : bhh[idx - cD];
}

// -------- fp16 tensor GEMM for ew: half C[E,4096] = A[E,128] @ B[128,4096] + bias --------
// CTA tile 128x128, full K=128 resident, 8 warps (2x4), warp tile 64x32, mma m16n8k16.
// smem: As [128 rows][136 halves], Bs [128 n][136 halves]  (pitch 136h = 68 words ≡ 4 mod 32)
#define EW_SMEM (128 * 136 * 2 * 2)
__global__ void __launch_bounds__(256) k_ewgemm(const __half* __restrict__ Ah,
                                                const __half* __restrict__ BTh,
                                                const float* __restrict__ bias,
                                                __half* __restrict__ C) {
    extern __shared__ __half ew_sm[];
    __half* As_h = ew_sm;                 // [128][136]
    __half* Bs_h = ew_sm + 128 * 136;     // [128][136]

    const int tid = threadIdx.x;
    const int warp = tid >> 5, lane = tid & 31;
    const int wm = warp >> 2, wn = warp & 3;
    const int g = lane >> 2, c = lane & 3;
    const int rowBase = blockIdx.y * 128;
    const int colBase = blockIdx.x * 128;

    // load A tile: 128 rows x 128 halves (16 x 16B chunks per row)
#pragma unroll
    for (int it = 0; it < 8; it++) {
        int idx = tid + it * 256;              // 0..2047
        int row = idx >> 4, q = idx & 15;
        int grow = rowBase + row;
        __half* dstp = As_h + row * 136 + q * 8;
        if (grow < cE) cp16(dstp, Ah + (size_t)grow * cH + q * 8);
        else *(uint4*)dstp = make_uint4(0u, 0u, 0u, 0u);
    }
    // load B tile: 128 n-rows x 128 halves
#pragma unroll
    for (int it = 0; it < 8; it++) {
        int idx = tid + it * 256;
        int n = idx >> 4, q = idx & 15;
        cp16(Bs_h + n * 136 + q * 8, BTh + (size_t)(colBase + n) * cH + q * 8);
    }
    asm volatile("cp.async.commit_group;");
    asm volatile("cp.async.wait_group 0;");
    __syncthreads();

    float acc[4][4][4];
#pragma unroll
    for (int mt = 0; mt < 4; mt++)
#pragma unroll
        for (int nt = 0; nt < 4; nt++)
#pragma unroll
            for (int j = 0; j < 4; j++) acc[mt][nt][j] = 0.0f;

#pragma unroll
    for (int ks = 0; ks < 8; ks++) {
        const int k0 = ks * 16;
        uint32_t af[4][4];
#pragma unroll
        for (int mt = 0; mt < 4; mt++) {
            int r = wm * 64 + mt * 16 + g;
            af[mt][0] = *(const uint32_t*)&As_h[r * 136 + k0 + 2 * c];
            af[mt][1] = *(const uint32_t*)&As_h[(r + 8) * 136 + k0 + 2 * c];
            af[mt][2] = *(const uint32_t*)&As_h[r * 136 + k0 + 2 * c + 8];
            af[mt][3] = *(const uint32_t*)&As_h[(r + 8) * 136 + k0 + 2 * c + 8];
        }
#pragma unroll
        for (int nt = 0; nt < 4; nt++) {
            int n = wn * 32 + nt * 8 + g;
            uint32_t bf[2];
            bf[0] = *(const uint32_t*)&Bs_h[n * 136 + k0 + 2 * c];
            bf[1] = *(const uint32_t*)&Bs_h[n * 136 + k0 + 2 * c + 8];
#pragma unroll
            for (int mt = 0; mt < 4; mt++)
                mma_f16(acc[mt][nt], af[mt], bf);
        }
    }

#pragma unroll
    for (int mt = 0; mt < 4; mt++) {
        int r0 = rowBase + wm * 64 + mt * 16 + g;
#pragma unroll
        for (int nt = 0; nt < 4; nt++) {
            int cc = colBase + wn * 32 + nt * 8 + c * 2;
            float b0 = bias[cc], b1 = bias[cc + 1];
            if (r0 < cE) {
                __half2 v = __floats2half2_rn(acc[mt][nt][0] + b0, acc[mt][nt][1] + b1);
                *(__half2*)(C + (size_t)r0 * cDSQ + cc) = v;
            }
            if (r0 + 8 < cE) {
                __half2 v = __floats2half2_rn(acc[mt][nt][2] + b0, acc[mt][nt][3] + b1);
                *(__half2*)(C + (size_t)(r0 + 8) * cDSQ + cc) = v;
            }
        }
    }
}

// -------- TF32 node GEMM core --------
#define NG_SMEM (64 * 132 * 4 + 64 * 68 * 4)

__device__ __forceinline__ void nodegemm_core(
    uint32_t (*As)[132], uint32_t (*Bs)[68],
    int M, int ldb, const float* __restrict__ Bw,
    const float* __restrict__ bias, float* __restrict__ Cp, int ldc,
    int rowBase, int colBase)
{
    const int tid = threadIdx.x;
    const int warp = tid >> 5, lane = tid & 31;
    const int g = lane >> 2, c = lane & 3;

    {
        int kr = tid >> 1, half = tid & 1;
        const float4* br = (const float4*)(Bw + (size_t)kr * ldb + colBase + half * 32);
#pragma unroll
        for (int q = 0; q < 8; q++) {
            float4 v = br[q];
            int nq = half * 8 + q;
            uint4 u;
            u.x = f2tf32(v.x); u.y = f2tf32(v.y); u.z = f2tf32(v.z); u.w = f2tf32(v.w);
            *(uint4*)&Bs[kr][nq * 4] = u;
        }
    }
    __syncthreads();

    float acc[2][8][4];
#pragma unroll
    for (int mt = 0; mt < 2; mt++)
#pragma unroll
        for (int nt = 0; nt < 8; nt++)
#pragma unroll
            for (int j = 0; j < 4; j++) acc[mt][nt][j] = 0.0f;

    const int r0 = warp * 32;
#pragma unroll
    for (int k0 = 0; k0 < 64; k0 += 8) {
        uint32_t af[2][4];
#pragma unroll
        for (int mt = 0; mt < 2; mt++) {
            int r = r0 + mt * 16 + g;
            af[mt][0] = As[k0 + c][r];
            af[mt][1] = As[k0 + c][r + 8];
            af[mt][2] = As[k0 + c + 4][r];
            af[mt][3] = As[k0 + c + 4][r + 8];
        }
#pragma unroll
        for (int nt = 0; nt < 8; nt++) {
            uint32_t bf[2];
            bf[0] = Bs[k0 + c][nt * 8 + g];
            bf[1] = Bs[k0 + c + 4][nt * 8 + g];
            mma_tf32(acc[0][nt], af[0], bf);
            mma_tf32(acc[1][nt], af[1], bf);
        }
    }

#pragma unroll
    for (int mt = 0; mt < 2; mt++) {
        int rr0 = rowBase + r0 + mt * 16 + g;
        int rr1 = rr0 + 8;
#pragma unroll
        for (int nt = 0; nt < 8; nt++) {
            int cc = colBase + nt * 8 + c * 2;
            float b0 = bias ? bias[cc] : 0.0f;
            float b1 = bias ? bias[cc + 1] : 0.0f;
            if (rr0 < M) {
                float2 v = make_float2(acc[mt][nt][0] + b0, acc[mt][nt][1] + b1);
                *(float2*)(Cp + (size_t)rr0 * ldc + cc) = v;
            }
            if (rr1 < M) {
                float2 v = make_float2(acc[mt][nt][2] + b0, acc[mt][nt][3] + b1);
                *(float2*)(Cp + (size_t)rr1 * ldc + cc) = v;
            }
        }
    }
}

__global__ void __launch_bounds__(128) k_nodegemm(int M, int ldb,
                                                  const float* __restrict__ A,
                                                  const float* __restrict__ Bw,
                                                  const float* __restrict__ bias,
                                                  float* __restrict__ Cp, int ldc) {
    extern __shared__ uint32_t ng_sm[];
    uint32_t (*As)[132] = (uint32_t (*)[132])ng_sm;
    uint32_t (*Bs)[68]  = (uint32_t (*)[68])(ng_sm + 64 * 132);
    const int tid = threadIdx.x;
    const int rowBase = blockIdx.y * 128;
    {
        int grow = rowBase + tid;
        if (grow < M) {
            const float4* ar = (const float4*)(A + (size_t)grow * cD);
#pragma unroll
            for (int q = 0; q < 16; q++) {
                float4 v = ar[q];
                As[q * 4 + 0][tid] = f2tf32(v.x);
                As[q * 4 + 1][tid] = f2tf32(v.y);
                As[q * 4 + 2][tid] = f2tf32(v.z);
                As[q * 4 + 3][tid] = f2tf32(v.w);
            }
        } else {
#pragma unroll
            for (int q = 0; q < 64; q++) As[q][tid] = 0u;
        }
    }
    nodegemm_core(As, Bs, M, ldb, Bw, bias, Cp, ldc, rowBase, blockIdx.x * 64);
}

__global__ void __launch_bounds__(128) k_mgemm(int M, int ldb,
                                               const float* __restrict__ agg,
                                               const float* __restrict__ CG,
                                               const float* __restrict__ deg,
                                               const float* __restrict__ cbias,
                                               const float* __restrict__ Bw,
                                               const float* __restrict__ bias,
                                               float* __restrict__ Cp, int ldc) {
    extern __shared__ uint32_t ng_sm[];
    uint32_t (*As)[132] = (uint32_t (*)[132])ng_sm;
    uint32_t (*Bs)[68]  = (uint32_t (*)[68])(ng_sm + 64 * 132);
    const int tid = threadIdx.x;
    const int rowBase = blockIdx.y * 128;
    {
        int grow = rowBase + tid;
        if (grow < M) {
            float inv = 1.0f / fmaxf(deg[grow], 1.0f);
            const float4* ag = (const float4*)(agg + (size_t)grow * cD);
            const float4* cg = (const float4*)(CG + (size_t)grow * 4 * cD);
            const float4* cb = (const float4*)(cbias);
#pragma unroll
            for (int q = 0; q < 16; q++) {
                float4 a = ag[q], cr = cg[q], bb = cb[q];
                As[q * 4 + 0][tid] = f2tf32(fmaxf(a.x * inv + cr.x + bb.x, 0.0f));
                As[q * 4 + 1][tid] = f2tf32(fmaxf(a.y * inv + cr.y + bb.y, 0.0f));
                As[q * 4 + 2][tid] = f2tf32(fmaxf(a.z * inv + cr.z + bb.z, 0.0f));
                As[q * 4 + 3][tid] = f2tf32(fmaxf(a.w * inv + cr.w + bb.w, 0.0f));
            }
        } else {
#pragma unroll
            for (int q = 0; q < 64; q++) As[q][tid] = 0u;
        }
    }
    nodegemm_core(As, Bs, M, ldb, Bw, bias, Cp, ldc, rowBase, blockIdx.x * 64);
}

// -------- per-edge matvec + scatter, vectorized 16B loads --------
__global__ void k_msg(const float* __restrict__ out, const __half* __restrict__ ew,
                      const int* __restrict__ src, const int* __restrict__ dst,
                      float* __restrict__ agg) {
    int e = blockIdx.x * blockDim.y + threadIdx.y;
    if (e >= cE) return;
    int lane = threadIdx.x;
    int s = src[e];
    float v_lo = __ldg(out + (size_t)s * cD + lane);
    float v_hi = __ldg(out + (size_t)s * cD + 32 + lane);
    const uint4* w = (const uint4*)(ew + (size_t)e * cDSQ);
    const int rl = lane >> 3, cl8 = lane & 7;
    float acc[8];
#pragma unroll
    for (int q = 0; q < 8; q++) acc[q] = 0.0f;

#pragma unroll
    for (int j = 0; j < 16; j++) {
        int row = j * 4 + rl;
        float side = (j < 8) ? v_lo : v_hi;
        float v = __shfl_sync(0xffffffffu, side, row & 31);
        uint4 u = w[row * 8 + cl8];
        __half2* h2 = (__half2*)&u;
#pragma unroll
        for (int q = 0; q < 4; q++) {
            float2 f = __half22float2(h2[q]);
            acc[q * 2]     += v * f.x;
            acc[q * 2 + 1] += v * f.y;
        }
    }
#pragma unroll
    for (int off = 8; off <= 16; off <<= 1)
#pragma unroll
        for (int q = 0; q < 8; q++)
            acc[q] += __shfl_xor_sync(0xffffffffu, acc[q], off);

    int dn = dst[e];
    int col = cl8 * 8 + rl * 2;
    atomicAdd(&agg[(size_t)dn * cD + col],     acc[rl * 2]);
    atomicAdd(&agg[(size_t)dn * cD + col + 1], acc[rl * 2 + 1]);
}

// GRU gates; also zeroes agg for the next step
__global__ void k_gate(const float* __restrict__ G1, const float* __restrict__ CG,
                       const float* __restrict__ h, float* __restrict__ hn,
                       float* __restrict__ agg) {
    int idx = blockIdx.x * blockDim.x + threadIdx.x;
    if (idx >= cN * cD) return;
    int n = idx >> 6, d = idx & 63;
    const float* g1 = G1 + (size_t)n * 3 * cD;
    const float* g2 = CG + (size_t)n * 4 * cD + cD;
    float r = sigm(g1[d] + g2[d]);
    float z = sigm(g1[cD + d] + g2[cD + d]);
    float nn = tanhf(g1[2 * cD + d] + r * g2[2 * cD + d]);
    hn[idx] = (1.0f - z) * nn + z * h[idx];
    agg[idx] = 0.0f;
}

// -------- fused Set2Set (3 iterations) + final lin1: one block per graph --------
__global__ void __launch_bounds__(128) k_set2set(
    const float* __restrict__ hfin, const int* __restrict__ batch,
    const float* __restrict__ w_ih, const float* __restrict__ w_hh,
    const float* __restrict__ b_ih, const float* __restrict__ b_hh,
    const float* __restrict__ l1w, const float* __restrict__ l1b,
    float* __restrict__ outp)
{
    const int b = blockIdx.x;
    const int tid = threadIdx.x, warp = tid >> 5, lane = tid & 31;
    __shared__ float s_qstar[128], s_g[256], s_q[64], s_cl[64], s_rvec[64];
    __shared__ float s_wmax[4], s_wsum[4];
    __shared__ float s_gmax, s_gsum;
    __shared__ int s_s, s_e;

    if (tid == 0) {
        int lo = 0, hi = cN;
        while (lo < hi) { int mid = (lo + hi) >> 1; if (batch[mid] < b) lo = mid + 1; else hi = mid; }
        s_s = lo;
        hi = cN;
        while (lo < hi) { int mid = (lo + hi) >> 1; if (batch[mid] < b + 1) lo = mid + 1; else hi = mid; }
        s_e = lo;
    }
    s_qstar[tid] = 0.0f;
    if (tid < 64) { s_q[tid] = 0.0f; s_cl[tid] = 0.0f; }
    __syncthreads();

    for (int t = 0; t < 3; t++) {
        float g0 = b_ih[tid] + b_hh[tid];
        float g1 = b_ih[tid + 128] + b_hh[tid + 128];
#pragma unroll 4
        for (int k = 0; k < 128; k++) {
            float qv = s_qstar[k];
            g0 += qv * w_ih[k * 256 + tid];
            g1 += qv * w_ih[k * 256 + tid + 128];
        }
#pragma unroll 4
        for (int k = 0; k < 64; k++) {
            float hv = s_q[k];
            g0 += hv * w_hh[k * 256 + tid];
            g1 += hv * w_hh[k * 256 + tid + 128];
        }
        s_g[tid] = g0; s_g[tid + 128] = g1;
        __syncthreads();
        if (tid < 64) {
            float ig = sigm(s_g[tid]), fg = sigm(s_g[64 + tid]);
            float gg = tanhf(s_g[128 + tid]), og = sigm(s_g[192 + tid]);
            float c = fg * s_cl[tid] + ig * gg;
            s_cl[tid] = c;
            s_q[tid] = og * tanhf(c);
            s_rvec[tid] = 0.0f;
        }
        __syncthreads();

        const int ns = s_s, ne = s_e;
        float wmax = -1e30f;
        for (int n = ns + warp; n < ne; n += 4) {
            const float* o = hfin + (size_t)n * cD;
            float d = o[lane] * s_q[lane] + o[32 + lane] * s_q[32 + lane];
#pragma unroll
            for (int off = 16; off; off >>= 1) d += __shfl_xor_sync(0xffffffffu, d, off);
            wmax = fmaxf(wmax, d);
        }
        if (lane == 0) s_wmax[warp] = wmax;
        __syncthreads();
        if (tid == 0)
            s_gmax = fmaxf(fmaxf(s_wmax[0], s_wmax[1]), fmaxf(s_wmax[2], s_wmax[3]));
        __syncthreads();
        const float gmax = s_gmax;

        float wsum = 0.0f, rv0 = 0.0f, rv1 = 0.0f;
        for (int n = ns + warp; n < ne; n += 4) {
            const float* o = hfin + (size_t)n * cD;
            float d = o[lane] * s_q[lane] + o[32 + lane] * s_q[32 + lane];
#pragma unroll
            for (int off = 16; off; off >>= 1) d += __shfl_xor_sync(0xffffffffu, d, off);
            float ee = expf(d - gmax);
            wsum += ee;
            rv0 += ee * o[lane];
            rv1 += ee * o[32 + lane];
        }
        if (lane == 0) s_wsum[warp] = wsum;
        atomicAdd(&s_rvec[lane], rv0);
        atomicAdd(&s_rvec[32 + lane], rv1);
        __syncthreads();
        if (tid == 0) s_gsum = s_wsum[0] + s_wsum[1] + s_wsum[2] + s_wsum[3];
        __syncthreads();

        if (tid < 64) s_qstar[tid] = s_q[tid];
        else {
            float denom = s_gsum;
            s_qstar[tid] = (denom > 0.0f) ? s_rvec[tid - 64] / denom : 0.0f;
        }
        __syncthreads();
    }

    if (tid < 64) {
        float acc = l1b[tid];
#pragma unroll 4
        for (int k = 0; k < 128; k++) acc += s_qstar[k] * l1w[k * cD + tid];
        outp[b * cD + tid] = fmaxf(acc, 0.0f);
    }
}

// ---------------- launch ----------------
extern "C" void kernel_launch(void* const* d_in, const int* in_sizes, int n_in,
                              void* d_out, int out_size) {
    const float* x        = (const float*)d_in[0];
    const float* ea       = (const float*)d_in[1];
    const int*   ei       = (const int*)d_in[2];
    const int*   batch    = (const int*)d_in[3];
    const float* lin0_w   = (const float*)d_in[4];
    const float* lin0_b   = (const float*)d_in[5];
    const float* net_w1   = (const float*)d_in[6];
    const float* net_b1   = (const float*)d_in[7];
    const float* net_w2   = (const float*)d_in[8];
    const float* net_b2   = (const float*)d_in[9];
    const float* conv_root= (const float*)d_in[10];
    const float* conv_bias= (const float*)d_in[11];
    const float* gru_w_ih = (const float*)d_in[12];
    const float* gru_w_hh = (const float*)d_in[13];
    const float* gru_b_ih = (const float*)d_in[14];
    const float* gru_b_hh = (const float*)d_in[15];
    const float* lstm_w_ih= (const float*)d_in[16];
    const float* lstm_w_hh= (const float*)d_in[17];
    const float* lstm_b_ih= (const float*)d_in[18];
    const float* lstm_b_hh= (const float*)d_in[19];
    const float* lin1_w   = (const float*)d_in[20];
    const float* lin1_b   = (const float*)d_in[21];
    float* out = (float*)d_out;

    const int* src = ei;
    const int* dst = ei + cE;

    void* p;
    cudaGetSymbolAddress(&p, g_h0);     float* p_h0 = (float*)p;
    cudaGetSymbolAddress(&p, g_h1);     float* p_h1 = (float*)p;
    cudaGetSymbolAddress(&p, g_hreluh); __half* p_hrh = (__half*)p;
    cudaGetSymbolAddress(&p, g_w2T);    __half* p_w2T = (__half*)p;
    cudaGetSymbolAddress(&p, g_ewh);    __half* p_ewh = (__half*)p;
    cudaGetSymbolAddress(&p, g_agg);    float* p_agg = (float*)p;
    cudaGetSymbolAddress(&p, g_CG);     float* p_CG = (float*)p;
    cudaGetSymbolAddress(&p, g_G1);     float* p_G1 = (float*)p;
    cudaGetSymbolAddress(&p, g_Wcat);   float* p_Wcat = (float*)p;
    cudaGetSymbolAddress(&p, g_bcat);   float* p_bcat = (float*)p;
    cudaGetSymbolAddress(&p, g_deg);    float* p_deg = (float*)p;

    const int T = 256;
    cudaFuncSetAttribute(k_ewgemm, cudaFuncAttributeMaxDynamicSharedMemorySize, EW_SMEM);
    cudaFuncSetAttribute(k_nodegemm, cudaFuncAttributeMaxDynamicSharedMemorySize, NG_SMEM);
    cudaFuncSetAttribute(k_mgemm, cudaFuncAttributeMaxDynamicSharedMemorySize, NG_SMEM);

    // degree
    k_deg_zero<<<(cN + T - 1) / T, T>>>(p_deg);
    k_deg<<<(cE + T - 1) / T, T>>>(dst, p_deg);

    // lin0 -> h0 (also zeroes agg)
    k_lin0<<<(cN * cD + T - 1) / T, T>>>(x, lin0_w, lin0_b, p_h0, p_agg);

    // edge net + preps
    k_edge1<<<(cE * cH + T - 1) / T, T>>>(ea, net_w1, net_b1, p_hrh);
    k_prepB<<<(cH * cDSQ + T - 1) / T, T>>>(net_w2, p_w2T);
    k_prepW<<<(cD * 4 * cD + T - 1) / T, T>>>(conv_root, gru_w_hh, gru_b_hh, p_Wcat, p_bcat);
    {
        dim3 grid(cDSQ / 128, (cE + 127) / 128);   // 32 x 313
        k_ewgemm<<<grid, 256, EW_SMEM>>>(p_hrh, p_w2T, net_b2, p_ewh);
    }

    // 3 message-passing steps
    for (int s = 0; s < 3; s++) {
        float* cur = (s & 1) ? p_h1 : p_h0;
        float* nxt = (s & 1) ? p_h0 : p_h1;

        {
            dim3 blk(32, 8);
            k_msg<<<(cE + 7) / 8, blk>>>(cur, p_ewh, src, dst, p_agg);
        }
        {
            dim3 grid(4, (cN + 127) / 128);
            k_nodegemm<<<grid, 128, NG_SMEM>>>(cN, 4 * cD, cur, p_Wcat, p_bcat, p_CG, 4 * cD);
        }
        {
            dim3 grid(3, (cN + 127) / 128);
            k_mgemm<<<grid, 128, NG_SMEM>>>(cN, 3 * cD, p_agg, p_CG, p_deg, conv_bias,
                                            gru_w_ih, gru_b_ih, p_G1, 3 * cD);
        }
        k_gate<<<(cN * cD + T - 1) / T, T>>>(p_G1, p_CG, cur, nxt, p_agg);
    }
    float* p_hfin = p_h1;

    // fused Set2Set (3 iterations) + lin1
    k_set2set<<<cB, 128>>>(p_hfin, batch, lstm_w_ih, lstm_w_hh, lstm_b_ih, lstm_b_hh,
                           lin1_w, lin1_b, out);
}